// round 5
// baseline (speedup 1.0000x reference)
#include <cuda_runtime.h>
#include <cuda_bf16.h>
#include <math.h>
#include <stdint.h>

#define BATCH 8
#define CDIM  512
#define INNER 256
#define QKV   768
#define HEADS 8
#define DH    32
#define HH    96
#define WW    96
#define HW    9216
#define NPOS  (BATCH*HW)   // 73728

// ---------------- scratch (position-major layouts) --------------------------
__device__ __nv_bfloat16 g_xh[(size_t)NPOS * CDIM];   // LN(x)^T hi  [pos][c]
__device__ __nv_bfloat16 g_xl[(size_t)NPOS * CDIM];   // LN(x)^T lo
__device__ float g_q1[(size_t)NPOS * QKV];            // qkv^T after 1x1
__device__ float g_q2[(size_t)NPOS * QKV];            // qkv^T after dwconv
__device__ __nv_bfloat16 g_ah[(size_t)NPOS * INNER];  // attn+silu hi
__device__ __nv_bfloat16 g_al[(size_t)NPOS * INNER];  // attn+silu lo
__device__ float g_zt[(size_t)NPOS * CDIM];           // z^T after out 1x1
__device__ __nv_bfloat16 g_wh [QKV * CDIM],  g_wl [QKV * CDIM];
__device__ __nv_bfloat16 g_owh[CDIM * INNER], g_owl[CDIM * INNER];
__device__ float g_kmax[BATCH * INNER], g_krsum[BATCH * INNER];
__device__ float g_ctx [BATCH * HEADS * DH * DH];
__device__ float g_ctxp[9 * BATCH * HEADS * DH * DH];

__device__ __forceinline__ void split_bf16(float v, __nv_bfloat16& h, __nv_bfloat16& l) {
    h = __float2bfloat16(v);
    l = __float2bfloat16(v - __bfloat162float(h));
}

// ---------------- weight conversion (row-major = K-major) -------------------
__global__ void convert_qkvw_kernel(const float* __restrict__ qw,
                                    const float* __restrict__ kw,
                                    const float* __restrict__ vw) {
    int i = blockIdx.x * blockDim.x + threadIdx.x;
    split_bf16(qw[i], g_wh[i], g_wl[i]);
    split_bf16(kw[i], g_wh[i + INNER*CDIM], g_wl[i + INNER*CDIM]);
    split_bf16(vw[i], g_wh[i + 2*INNER*CDIM], g_wl[i + 2*INNER*CDIM]);
}
__global__ void convert_outw_kernel(const float* __restrict__ ow) {
    int i = blockIdx.x * blockDim.x + threadIdx.x;
    split_bf16(ow[i], g_owh[i], g_owl[i]);
}

// ---------------- input LN: NCHW -> x^T hi/lo (smem transpose) --------------
__global__ void ln_in_t_kernel(const float* __restrict__ x,
                               const float* __restrict__ g) {
    extern __shared__ float s[];            // [512][33]
    __shared__ float s_mean[32], s_r[32];
    int t = threadIdx.x;
    int pos0 = blockIdx.x * 32;
    int b = pos0 / HW;
    int hw0 = pos0 - b * HW;
    int lane = t & 31, crow = t >> 5;
    #pragma unroll 8
    for (int it = 0; it < 64; it++) {
        int c = crow + it * 8;
        s[c * 33 + lane] = x[((size_t)b * CDIM + c) * HW + hw0 + lane];
    }
    __syncthreads();
    int p = t >> 3, sub = t & 7;
    float sm = 0.f, sq = 0.f;
    #pragma unroll 8
    for (int j = 0; j < 64; j++) {
        float v = s[(sub + j * 8) * 33 + p];
        sm += v; sq += v * v;
    }
    #pragma unroll
    for (int off = 4; off > 0; off >>= 1) {
        sm += __shfl_xor_sync(0xffffffffu, sm, off);
        sq += __shfl_xor_sync(0xffffffffu, sq, off);
    }
    float mean = sm * (1.f / CDIM);
    float var  = sq * (1.f / CDIM) - mean * mean;
    float r = rsqrtf(var + 1e-5f);
    if (sub == 0) { s_mean[p] = mean; s_r[p] = r; }
    __syncthreads();
    int c64 = t & 63, pq = t >> 6;
    #pragma unroll
    for (int pp = 0; pp < 8; pp++) {
        int p2 = pq * 8 + pp;
        float m2 = s_mean[p2], r2 = s_r[p2];
        size_t row = (size_t)(pos0 + p2) * CDIM;
        #pragma unroll
        for (int it = 0; it < 8; it++) {
            int c = c64 + it * 64;
            float y = (s[c * 33 + p2] - m2) * r2 * g[c];
            split_bf16(y, g_xh[row + c], g_xl[row + c]);
        }
    }
}

// ---------------- output LN: z^T -> NCHW out --------------------------------
__global__ void ln_out_t_kernel(const float* __restrict__ g,
                                float* __restrict__ out) {
    extern __shared__ float s[];            // [512][33]
    __shared__ float s_mean[32], s_r[32];
    int t = threadIdx.x;
    int pos0 = blockIdx.x * 32;
    int b = pos0 / HW;
    int hw0 = pos0 - b * HW;
    int c64 = t & 63, pq = t >> 6;
    #pragma unroll
    for (int pp = 0; pp < 8; pp++) {
        int p2 = pq * 8 + pp;
        size_t row = (size_t)(pos0 + p2) * CDIM;
        #pragma unroll
        for (int it = 0; it < 8; it++) {
            int c = c64 + it * 64;
            s[c * 33 + p2] = g_zt[row + c];
        }
    }
    __syncthreads();
    int p = t >> 3, sub = t & 7;
    float sm = 0.f, sq = 0.f;
    #pragma unroll 8
    for (int j = 0; j < 64; j++) {
        float v = s[(sub + j * 8) * 33 + p];
        sm += v; sq += v * v;
    }
    #pragma unroll
    for (int off = 4; off > 0; off >>= 1) {
        sm += __shfl_xor_sync(0xffffffffu, sm, off);
        sq += __shfl_xor_sync(0xffffffffu, sq, off);
    }
    float mean = sm * (1.f / CDIM);
    float var  = sq * (1.f / CDIM) - mean * mean;
    float r = rsqrtf(var + 1e-5f);
    if (sub == 0) { s_mean[p] = mean; s_r[p] = r; }
    __syncthreads();
    int lane = t & 31, crow = t >> 5;
    #pragma unroll 8
    for (int it = 0; it < 64; it++) {
        int c = crow + it * 8;
        out[((size_t)b * CDIM + c) * HW + hw0 + lane] =
            (s[c * 33 + lane] - s_mean[lane]) * s_r[lane] * g[c];
    }
}

// ---------------- mma.sync bf16 GEMM (3-term split), position-major ---------
// Y[pos, n] = sum_k A[pos,k] * B[n,k].  A,B both K-major -> non-trans ldmatrix.
__device__ __forceinline__ uint32_t sptr(const void* p) {
    return (uint32_t)__cvta_generic_to_shared(p);
}
__device__ __forceinline__ void cp_async16(uint32_t sm, const void* gm) {
    asm volatile("cp.async.cg.shared.global [%0], [%1], 16;\n" :: "r"(sm), "l"(gm));
}
__device__ __forceinline__ void ldsm_x4(uint32_t* r, uint32_t a) {
    asm volatile("ldmatrix.sync.aligned.m8n8.x4.shared.b16 {%0,%1,%2,%3}, [%4];"
                 : "=r"(r[0]), "=r"(r[1]), "=r"(r[2]), "=r"(r[3]) : "r"(a));
}
__device__ __forceinline__ void ldsm_x2(uint32_t* r, uint32_t a) {
    asm volatile("ldmatrix.sync.aligned.m8n8.x2.shared.b16 {%0,%1}, [%2];"
                 : "=r"(r[0]), "=r"(r[1]) : "r"(a));
}
__device__ __forceinline__ void mma_bf16(float* c, const uint32_t* a, const uint32_t* b) {
    asm volatile("mma.sync.aligned.m16n8k16.row.col.f32.bf16.bf16.f32 "
                 "{%0,%1,%2,%3},{%4,%5,%6,%7},{%8,%9},{%0,%1,%2,%3};"
                 : "+f"(c[0]), "+f"(c[1]), "+f"(c[2]), "+f"(c[3])
                 : "r"(a[0]), "r"(a[1]), "r"(a[2]), "r"(a[3]), "r"(b[0]), "r"(b[1]));
}

template<int K, int NOUT>
__device__ __forceinline__ void hgemm_t(const __nv_bfloat16* __restrict__ Ah,
                                        const __nv_bfloat16* __restrict__ Al,
                                        const __nv_bfloat16* __restrict__ Bh,
                                        const __nv_bfloat16* __restrict__ Bl,
                                        float* __restrict__ Y) {
    constexpr int BM = 128, BK = 32;
    constexpr int AP = BK + 8;            // 40 halves (80B): conflict-free ldsm
    constexpr int PLANE = BM * AP;        // 5120 halves per plane
    constexpr int STAGE = 4 * PLANE;      // Ah, Al, Bh, Bl
    constexpr int KC = K / BK;
    extern __shared__ __nv_bfloat16 smem[];

    int t = threadIdx.x, lane = t & 31, warp = t >> 5;
    int m0 = blockIdx.y * BM;
    int n0 = blockIdx.x * BM;             // BN == BM == 128
    int wm = (warp & 1) * 64, wn = (warp >> 1) * 32;

    auto load_stage = [&](int kc, int s) {
        __nv_bfloat16* base = smem + (size_t)s * STAGE;
        int k0 = kc * BK;
        #pragma unroll
        for (int i = 0; i < 2; i++) {
            int c = t + i * 256;          // 0..511
            int row = c >> 2, kk = (c & 3) * 8;
            uint32_t dst = sptr(&base[row * AP + kk]);
            cp_async16(dst,                       &Ah[(size_t)(m0 + row) * K + k0 + kk]);
            cp_async16(dst + PLANE * 2,           &Al[(size_t)(m0 + row) * K + k0 + kk]);
            cp_async16(dst + 2 * PLANE * 2,       &Bh[(size_t)(n0 + row) * K + k0 + kk]);
            cp_async16(dst + 3 * PLANE * 2,       &Bl[(size_t)(n0 + row) * K + k0 + kk]);
        }
        asm volatile("cp.async.commit_group;");
    };

    float acc[4][4][4];
    #pragma unroll
    for (int i = 0; i < 4; i++)
        #pragma unroll
        for (int j = 0; j < 4; j++)
            #pragma unroll
            for (int r = 0; r < 4; r++) acc[i][j][r] = 0.f;

    load_stage(0, 0);
    for (int kc = 0; kc < KC; kc++) {
        int s = kc & 1;
        asm volatile("cp.async.wait_group 0;");
        __syncthreads();
        if (kc + 1 < KC) load_stage(kc + 1, s ^ 1);

        __nv_bfloat16* sa_h = smem + (size_t)s * STAGE;
        __nv_bfloat16* sa_l = sa_h + PLANE;
        __nv_bfloat16* sb_h = sa_l + PLANE;
        __nv_bfloat16* sb_l = sb_h + PLANE;

        #pragma unroll
        for (int ks = 0; ks < 2; ks++) {
            // B frags: [n][k] non-trans x2 -> k16n8 col operand
            uint32_t bh[4][2], bl[4][2];
            int br = wn + (lane & 7), bsel = ((lane >> 3) & 1) * 8;
            int bcol = ks * 16 + bsel;
            #pragma unroll
            for (int nt = 0; nt < 4; nt++) {
                ldsm_x2(bh[nt], sptr(&sb_h[(br + nt * 8) * AP + bcol]));
                ldsm_x2(bl[nt], sptr(&sb_l[(br + nt * 8) * AP + bcol]));
            }
            // A frags
            uint32_t a[4][4];
            int arow = lane & 15;
            int acol = ks * 16 + (lane >> 4) * 8;
            #pragma unroll
            for (int mt = 0; mt < 4; mt++)
                ldsm_x4(a[mt], sptr(&sa_h[(wm + mt * 16 + arow) * AP + acol]));
            #pragma unroll
            for (int mt = 0; mt < 4; mt++)
                #pragma unroll
                for (int nt = 0; nt < 4; nt++) {
                    mma_bf16(acc[mt][nt], a[mt], bh[nt]);
                    mma_bf16(acc[mt][nt], a[mt], bl[nt]);
                }
            #pragma unroll
            for (int mt = 0; mt < 4; mt++)
                ldsm_x4(a[mt], sptr(&sa_l[(wm + mt * 16 + arow) * AP + acol]));
            #pragma unroll
            for (int mt = 0; mt < 4; mt++)
                #pragma unroll
                for (int nt = 0; nt < 4; nt++)
                    mma_bf16(acc[mt][nt], a[mt], bh[nt]);
        }
        __syncthreads();
    }

    #pragma unroll
    for (int mt = 0; mt < 4; mt++)
        #pragma unroll
        for (int nt = 0; nt < 4; nt++) {
            int pos = m0 + wm + mt * 16 + (lane >> 2);
            int n   = n0 + wn + nt * 8 + (lane & 3) * 2;
            *(float2*)&Y[(size_t)pos * NOUT + n] =
                make_float2(acc[mt][nt][0], acc[mt][nt][1]);
            *(float2*)&Y[(size_t)(pos + 8) * NOUT + n] =
                make_float2(acc[mt][nt][2], acc[mt][nt][3]);
        }
}

__global__ void __launch_bounds__(256) gemm1_kernel() {
    hgemm_t<CDIM, QKV>(g_xh, g_xl, g_wh, g_wl, g_q1);
}
__global__ void __launch_bounds__(256) gemm2_kernel() {
    hgemm_t<INNER, CDIM>(g_ah, g_al, g_owh, g_owl, g_zt);
}

// ---------------- depthwise 3x3 on position-major layout --------------------
__global__ void dwconv_t_kernel(const float* __restrict__ qwd,
                                const float* __restrict__ kwd,
                                const float* __restrict__ vwd) {
    int h = blockIdx.x, b = blockIdx.y, t = threadIdx.x;
    bool hm = h > 0, hp = h < HH - 1;
    size_t rowm = ((size_t)b * HW + (size_t)(h - 1) * WW) * QKV;
    size_t row0 = ((size_t)b * HW + (size_t)h * WW) * QKV;
    size_t rowp = ((size_t)b * HW + (size_t)(h + 1) * WW) * QKV;
    #pragma unroll
    for (int cc = 0; cc < 3; cc++) {
        int c = t + cc * 256;
        const float* wp = (c < 256) ? (qwd + c * 9)
                        : (c < 512) ? (kwd + (c - 256) * 9)
                                    : (vwd + (c - 512) * 9);
        float wt[9];
        #pragma unroll
        for (int i = 0; i < 9; i++) wt[i] = wp[i];
        float cm[3] = {0.f, 0.f, 0.f};
        float c0[3], cp[3];
        c0[0] = hm ? g_q1[rowm + c] : 0.f;
        c0[1] = g_q1[row0 + c];
        c0[2] = hp ? g_q1[rowp + c] : 0.f;
        for (int w = 0; w < WW; w++) {
            if (w < WW - 1) {
                size_t off = (size_t)(w + 1) * QKV + c;
                cp[0] = hm ? g_q1[rowm + off] : 0.f;
                cp[1] = g_q1[row0 + off];
                cp[2] = hp ? g_q1[rowp + off] : 0.f;
            } else { cp[0] = cp[1] = cp[2] = 0.f; }
            float o = wt[0] * cm[0] + wt[1] * c0[0] + wt[2] * cp[0]
                    + wt[3] * cm[1] + wt[4] * c0[1] + wt[5] * cp[1]
                    + wt[6] * cm[2] + wt[7] * c0[2] + wt[8] * cp[2];
            g_q2[row0 + (size_t)w * QKV + c] = o;
            cm[0] = c0[0]; cm[1] = c0[1]; cm[2] = c0[2];
            c0[0] = cp[0]; c0[1] = cp[1]; c0[2] = cp[2];
        }
    }
}

// ---------------- k softmax stats (online max/sum over positions) -----------
__global__ void kstats_t_kernel() {
    int b = blockIdx.y;
    int c0 = blockIdx.x * 64;
    int t = threadIdx.x;
    int c = c0 + (t & 63), pth = t >> 6;
    __shared__ float smax[256], ssum[256];
    float m = -1e30f, s = 0.f;
    for (int p = pth; p < HW; p += 4) {
        float v = g_q2[((size_t)b * HW + p) * QKV + INNER + c];
        if (v > m) { s = s * __expf(m - v) + 1.f; m = v; }
        else s += __expf(v - m);
    }
    smax[t] = m; ssum[t] = s;
    __syncthreads();
    if (t < 64) {
        float M = smax[t], S = ssum[t];
        #pragma unroll
        for (int q = 1; q < 4; q++) {
            float m2 = smax[t + q * 64], s2 = ssum[t + q * 64];
            float Mn = fmaxf(M, m2);
            S = S * __expf(M - Mn) + s2 * __expf(m2 - Mn);
            M = Mn;
        }
        g_kmax [b * INNER + c0 + t] = M;
        g_krsum[b * INNER + c0 + t] = 1.f / S;
    }
}

// ---------------- context = softmax_k^T @ v (partials over 9 chunks) --------
__global__ void context_part_t_kernel() {
    int bh = blockIdx.x, chunk = blockIdx.y;
    int b = bh >> 3, h = bh & 7;
    const float* km = g_kmax  + b * INNER + h * DH;
    const float* kr = g_krsum + b * INNER + h * DH;
    __shared__ float sk[DH][33];
    __shared__ float sv[DH][33];
    int t = threadIdx.x;
    int e = t & 31, d0 = (t >> 5) * 4;
    float a0 = 0.f, a1 = 0.f, a2 = 0.f, a3 = 0.f;
    int nbeg = chunk * 1024, nend = nbeg + 1024;
    for (int p0 = nbeg; p0 < nend; p0 += 32) {
        #pragma unroll
        for (int i = 0; i < 4; i++) {
            int j = t + i * 256;
            int p = j >> 5, col = j & 31;
            size_t rb = ((size_t)b * HW + p0 + p) * QKV;
            float kv = g_q2[rb + INNER + h * DH + col];
            sk[col][p] = __expf(kv - km[col]) * kr[col];
            sv[col][p] = g_q2[rb + 2 * INNER + h * DH + col];
        }
        __syncthreads();
        #pragma unroll
        for (int p = 0; p < 32; p++) {
            float vv = sv[e][p];
            a0 += sk[d0 + 0][p] * vv;
            a1 += sk[d0 + 1][p] * vv;
            a2 += sk[d0 + 2][p] * vv;
            a3 += sk[d0 + 3][p] * vv;
        }
        __syncthreads();
    }
    float* cp = g_ctxp + ((size_t)chunk * BATCH * HEADS + bh) * DH * DH;
    cp[(d0 + 0) * DH + e] = a0;
    cp[(d0 + 1) * DH + e] = a1;
    cp[(d0 + 2) * DH + e] = a2;
    cp[(d0 + 3) * DH + e] = a3;
}
__global__ void context_reduce_kernel() {
    int bh = blockIdx.x;
    int i = threadIdx.x;
    float s = 0.f;
    #pragma unroll
    for (int c = 0; c < 9; c++)
        s += g_ctxp[((size_t)c * BATCH * HEADS + bh) * DH * DH + i];
    g_ctx[(size_t)bh * DH * DH + i] = s;
}

// ---------------- q softmax @ context + silu (position-major) ---------------
__global__ void qattn_t_kernel() {
    __shared__ float sctx[HEADS * DH * DH];   // 32 KB
    int t = threadIdx.x;
    int p0 = blockIdx.x * 8;
    int b = p0 / HW;
    for (int i = t; i < HEADS * DH * DH; i += 256)
        sctx[i] = g_ctx[(size_t)b * HEADS * DH * DH + i];
    __syncthreads();
    int wid = t >> 5, lane = t & 31;
    size_t prow = (size_t)(p0 + wid) * QKV;
    size_t orow = (size_t)(p0 + wid) * INNER;
    #pragma unroll
    for (int h = 0; h < HEADS; h++) {
        float qv = g_q2[prow + h * DH + lane];
        float m = qv;
        #pragma unroll
        for (int off = 16; off > 0; off >>= 1)
            m = fmaxf(m, __shfl_xor_sync(0xffffffffu, m, off));
        float ev = __expf(qv - m);
        float s = ev;
        #pragma unroll
        for (int off = 16; off > 0; off >>= 1)
            s += __shfl_xor_sync(0xffffffffu, s, off);
        float qd = ev * (0.17677669529663688f / s);
        float o = 0.f;
        #pragma unroll
        for (int d = 0; d < DH; d++)
            o += __shfl_sync(0xffffffffu, qd, d) * sctx[h * DH * DH + d * DH + lane];
        o = o / (1.f + __expf(-o));
        split_bf16(o, g_ah[orow + h * DH + lane], g_al[orow + h * DH + lane]);
    }
}

// ---------------- launch ----------------------------------------------------
extern "C" void kernel_launch(void* const* d_in, const int* in_sizes, int n_in,
                              void* d_out, int out_size) {
    const float* fmap       = (const float*)d_in[0];
    const float* norm_g     = (const float*)d_in[1];
    const float* q_w1       = (const float*)d_in[2];
    const float* q_wd       = (const float*)d_in[3];
    const float* k_w1       = (const float*)d_in[4];
    const float* k_wd       = (const float*)d_in[5];
    const float* v_w1       = (const float*)d_in[6];
    const float* v_wd       = (const float*)d_in[7];
    const float* out_w      = (const float*)d_in[8];
    const float* out_norm_g = (const float*)d_in[9];
    float* out = (float*)d_out;

    // GEMM smem: 2 stages * 4 planes * 128*40 halves * 2B = 81920
    const int GEMM_SMEM = 2 * 4 * 128 * 40 * 2;
    const int LN_SMEM = 512 * 33 * 4;           // 67584
    cudaFuncSetAttribute(gemm1_kernel, cudaFuncAttributeMaxDynamicSharedMemorySize, GEMM_SMEM);
    cudaFuncSetAttribute(gemm2_kernel, cudaFuncAttributeMaxDynamicSharedMemorySize, GEMM_SMEM);
    cudaFuncSetAttribute(ln_in_t_kernel, cudaFuncAttributeMaxDynamicSharedMemorySize, LN_SMEM);
    cudaFuncSetAttribute(ln_out_t_kernel, cudaFuncAttributeMaxDynamicSharedMemorySize, LN_SMEM);

    convert_qkvw_kernel<<<(INNER * CDIM) / 256, 256>>>(q_w1, k_w1, v_w1);
    convert_outw_kernel<<<(CDIM * INNER) / 256, 256>>>(out_w);

    ln_in_t_kernel<<<NPOS / 32, 256, LN_SMEM>>>(fmap, norm_g);

    gemm1_kernel<<<dim3(QKV / 128, NPOS / 128), 256, GEMM_SMEM>>>();

    dwconv_t_kernel<<<dim3(HH, BATCH), 256>>>(q_wd, k_wd, v_wd);

    kstats_t_kernel<<<dim3(INNER / 64, BATCH), 256>>>();
    context_part_t_kernel<<<dim3(BATCH * HEADS, 9), 256>>>();
    context_reduce_kernel<<<BATCH * HEADS, 1024>>>();
    qattn_t_kernel<<<NPOS / 8, 256>>>();

    gemm2_kernel<<<dim3(CDIM / 128, NPOS / 128), 256, GEMM_SMEM>>>();

    ln_out_t_kernel<<<NPOS / 32, 256, LN_SMEM>>>(out_norm_g, out);
}

// round 6
// speedup vs baseline: 1.2969x; 1.2969x over previous
#include <cuda_runtime.h>
#include <cuda_bf16.h>
#include <math.h>
#include <stdint.h>

#define BATCH 8
#define CDIM  512
#define INNER 256
#define QKV   768
#define HEADS 8
#define DH    32
#define HH    96
#define WW    96
#define HW    9216   // 96*96

// ---------------- scratch (static device globals) ---------------------------
__device__ __nv_bfloat16 g_xh [(size_t)BATCH * CDIM  * HW];  // LN(x) hi
__device__ __nv_bfloat16 g_xl [(size_t)BATCH * CDIM  * HW];  // LN(x) lo
__device__ float g_qkv1[(size_t)BATCH * QKV   * HW];          // after 1x1
__device__ float g_qkv2[(size_t)BATCH * QKV   * HW];          // after dwconv3
__device__ __nv_bfloat16 g_ah [(size_t)BATCH * INNER * HW];   // attn+silu hi
__device__ __nv_bfloat16 g_al [(size_t)BATCH * INNER * HW];   // attn+silu lo
__device__ float g_z   [(size_t)BATCH * CDIM  * HW];          // after out conv1x1
__device__ __nv_bfloat16 g_wh [(size_t)QKV * CDIM];           // qkv weights hi
__device__ __nv_bfloat16 g_wl [(size_t)QKV * CDIM];           // qkv weights lo
__device__ __nv_bfloat16 g_owh[(size_t)CDIM * INNER];         // out weights hi
__device__ __nv_bfloat16 g_owl[(size_t)CDIM * INNER];         // out weights lo
__device__ float g_kmax [BATCH * INNER];
__device__ float g_krsum[BATCH * INNER];
__device__ float g_ctx  [BATCH * HEADS * DH * DH];
__device__ float g_ctxp [(size_t)9 * BATCH * HEADS * DH * DH];

__device__ __forceinline__ void split_bf16(float v, __nv_bfloat16& h, __nv_bfloat16& l) {
    h = __float2bfloat16(v);
    l = __float2bfloat16(v - __bfloat162float(h));
}

// ---------------- weight conversion ----------------------------------------
__global__ void convert_qkvw_kernel(const float* __restrict__ qw,
                                    const float* __restrict__ kw,
                                    const float* __restrict__ vw) {
    int i = blockIdx.x * blockDim.x + threadIdx.x;  // 0 .. INNER*CDIM-1
    split_bf16(qw[i], g_wh[i], g_wl[i]);
    split_bf16(kw[i], g_wh[i + INNER*CDIM], g_wl[i + INNER*CDIM]);
    split_bf16(vw[i], g_wh[i + 2*INNER*CDIM], g_wl[i + 2*INNER*CDIM]);
}
__global__ void convert_outw_kernel(const float* __restrict__ ow) {
    int i = blockIdx.x * blockDim.x + threadIdx.x;  // 0 .. CDIM*INNER-1
    split_bf16(ow[i], g_owh[i], g_owl[i]);
}

// ---------------- single-pass channel LNs (smem-buffered) -------------------
// Block: 256 threads, 32 positions x 512 channels buffered in smem (one read).
__global__ void ln_in_kernel(const float* __restrict__ x,
                             const float* __restrict__ g) {
    extern __shared__ float s[];            // [512][33]
    __shared__ float s_mean[32], s_r[32];
    int t = threadIdx.x;
    int pos0 = blockIdx.x * 32;
    int b = pos0 / HW;
    int hw0 = pos0 - b * HW;
    int lane = t & 31, crow = t >> 5;
    #pragma unroll 8
    for (int it = 0; it < 64; it++) {
        int c = crow + it * 8;
        s[c * 33 + lane] = x[((size_t)b * CDIM + c) * HW + hw0 + lane];
    }
    __syncthreads();
    int p = t >> 3, sub = t & 7;            // 8 threads per position
    float sm = 0.f, sq = 0.f;
    #pragma unroll 8
    for (int j = 0; j < 64; j++) {
        float v = s[(sub + j * 8) * 33 + p];
        sm += v; sq += v * v;
    }
    #pragma unroll
    for (int off = 4; off > 0; off >>= 1) {
        sm += __shfl_xor_sync(0xffffffffu, sm, off);
        sq += __shfl_xor_sync(0xffffffffu, sq, off);
    }
    float mean = sm * (1.f / CDIM);
    float var  = sq * (1.f / CDIM) - mean * mean;
    float r = rsqrtf(var + 1e-5f);
    if (sub == 0) { s_mean[p] = mean; s_r[p] = r; }
    __syncthreads();
    float m2 = s_mean[lane], r2 = s_r[lane];
    #pragma unroll 8
    for (int it = 0; it < 64; it++) {
        int c = crow + it * 8;
        float y = (s[c * 33 + lane] - m2) * r2 * g[c];
        size_t o = ((size_t)b * CDIM + c) * HW + hw0 + lane;
        split_bf16(y, g_xh[o], g_xl[o]);
    }
}

__global__ void ln_out_kernel(const float* __restrict__ g,
                              float* __restrict__ out) {
    extern __shared__ float s[];            // [512][33]
    __shared__ float s_mean[32], s_r[32];
    int t = threadIdx.x;
    int pos0 = blockIdx.x * 32;
    int b = pos0 / HW;
    int hw0 = pos0 - b * HW;
    int lane = t & 31, crow = t >> 5;
    #pragma unroll 8
    for (int it = 0; it < 64; it++) {
        int c = crow + it * 8;
        s[c * 33 + lane] = g_z[((size_t)b * CDIM + c) * HW + hw0 + lane];
    }
    __syncthreads();
    int p = t >> 3, sub = t & 7;
    float sm = 0.f, sq = 0.f;
    #pragma unroll 8
    for (int j = 0; j < 64; j++) {
        float v = s[(sub + j * 8) * 33 + p];
        sm += v; sq += v * v;
    }
    #pragma unroll
    for (int off = 4; off > 0; off >>= 1) {
        sm += __shfl_xor_sync(0xffffffffu, sm, off);
        sq += __shfl_xor_sync(0xffffffffu, sq, off);
    }
    float mean = sm * (1.f / CDIM);
    float var  = sq * (1.f / CDIM) - mean * mean;
    float r = rsqrtf(var + 1e-5f);
    if (sub == 0) { s_mean[p] = mean; s_r[p] = r; }
    __syncthreads();
    float m2 = s_mean[lane], r2 = s_r[lane];
    #pragma unroll 8
    for (int it = 0; it < 64; it++) {
        int c = crow + it * 8;
        out[((size_t)b * CDIM + c) * HW + hw0 + lane] =
            (s[c * 33 + lane] - m2) * r2 * g[c];
    }
}

// ---------------- tensor-core GEMM (3-term bf16 split, 3-stage pipe) -------
// Y[b] = A[M,K] @ X[b][K,N], N = HW. CTA tile 128x128x32, 8 warps of 64x32.
__device__ __forceinline__ uint32_t sptr(const void* p) {
    return (uint32_t)__cvta_generic_to_shared(p);
}
__device__ __forceinline__ void cp_async16(void* sm, const void* gm) {
    asm volatile("cp.async.cg.shared.global [%0], [%1], 16;\n"
                 :: "r"(sptr(sm)), "l"(gm));
}
__device__ __forceinline__ void ldsm_x4(uint32_t* r, uint32_t a) {
    asm volatile("ldmatrix.sync.aligned.m8n8.x4.shared.b16 {%0,%1,%2,%3}, [%4];"
                 : "=r"(r[0]), "=r"(r[1]), "=r"(r[2]), "=r"(r[3]) : "r"(a));
}
__device__ __forceinline__ void ldsm_x2t(uint32_t* r, uint32_t a) {
    asm volatile("ldmatrix.sync.aligned.m8n8.x2.trans.shared.b16 {%0,%1}, [%2];"
                 : "=r"(r[0]), "=r"(r[1]) : "r"(a));
}
__device__ __forceinline__ void mma_bf16(float* c, const uint32_t* a, const uint32_t* b) {
    asm volatile("mma.sync.aligned.m16n8k16.row.col.f32.bf16.bf16.f32 "
                 "{%0,%1,%2,%3},{%4,%5,%6,%7},{%8,%9},{%0,%1,%2,%3};"
                 : "+f"(c[0]), "+f"(c[1]), "+f"(c[2]), "+f"(c[3])
                 : "r"(a[0]), "r"(a[1]), "r"(a[2]), "r"(a[3]), "r"(b[0]), "r"(b[1]));
}

template<int M, int K>
__device__ __forceinline__ void mma_gemm_body(const __nv_bfloat16* __restrict__ Ah,
                                              const __nv_bfloat16* __restrict__ Al,
                                              const __nv_bfloat16* __restrict__ Xh,
                                              const __nv_bfloat16* __restrict__ Xl,
                                              float* __restrict__ Y) {
    constexpr int N = HW;
    constexpr int BM = 128, BN = 128, BK = 32;
    constexpr int AP = BK + 8;      // 40 halves/row (80B): conflict-free ldsm
    constexpr int BP = BN + 8;      // 136 halves/row (272B)
    constexpr int A_SZ = BM * AP;   // 5120 halves
    constexpr int B_SZ = BK * BP;   // 4352 halves
    constexpr int STAGE = 2 * A_SZ + 2 * B_SZ;   // 18944 halves = 37888 B
    constexpr int KC = K / BK;
    extern __shared__ __nv_bfloat16 smem[];

    int b = blockIdx.z;
    const __nv_bfloat16* XhB = Xh + (size_t)b * K * N;
    const __nv_bfloat16* XlB = Xl + (size_t)b * K * N;
    float* Yb = Y + (size_t)b * M * N;
    int tm0 = blockIdx.y * BM;
    int tn0 = blockIdx.x * BN;
    int t = threadIdx.x;
    int lane = t & 31, warp = t >> 5;
    int wm = (warp & 1) * 64, wn = (warp >> 1) * 32;

    auto load_stage = [&](int kc, int s) {
        __nv_bfloat16* sa_h = smem + (size_t)s * STAGE;
        __nv_bfloat16* sa_l = sa_h + A_SZ;
        __nv_bfloat16* sb_h = sa_l + A_SZ;
        __nv_bfloat16* sb_l = sb_h + B_SZ;
        int k0 = kc * BK;
        #pragma unroll
        for (int i = 0; i < 2; i++) {
            int c = t + i * 256;
            int m  = c >> 2, kk = (c & 3) * 8;
            cp_async16(&sa_h[m * AP + kk], &Ah[(size_t)(tm0 + m) * K + k0 + kk]);
            cp_async16(&sa_l[m * AP + kk], &Al[(size_t)(tm0 + m) * K + k0 + kk]);
            int kr = c >> 4, nn = (c & 15) * 8;
            cp_async16(&sb_h[kr * BP + nn], &XhB[(size_t)(k0 + kr) * N + tn0 + nn]);
            cp_async16(&sb_l[kr * BP + nn], &XlB[(size_t)(k0 + kr) * N + tn0 + nn]);
        }
        asm volatile("cp.async.commit_group;");
    };

    float acc[4][4][4];
    #pragma unroll
    for (int i = 0; i < 4; i++)
        #pragma unroll
        for (int j = 0; j < 4; j++)
            #pragma unroll
            for (int r = 0; r < 4; r++) acc[i][j][r] = 0.f;

    load_stage(0, 0);
    load_stage(1, 1);
    for (int kc = 0; kc < KC; kc++) {
        int s = kc % 3;
        if (kc + 1 < KC) asm volatile("cp.async.wait_group 1;");
        else             asm volatile("cp.async.wait_group 0;");
        __syncthreads();
        if (kc + 2 < KC) load_stage(kc + 2, (kc + 2) % 3);

        __nv_bfloat16* sa_h = smem + (size_t)s * STAGE;
        __nv_bfloat16* sa_l = sa_h + A_SZ;
        __nv_bfloat16* sb_h = sa_l + A_SZ;
        __nv_bfloat16* sb_l = sb_h + B_SZ;

        #pragma unroll
        for (int ks = 0; ks < 2; ks++) {
            uint32_t bh[4][2], bl[4][2];
            int brow = ks * 16 + (lane & 15);
            #pragma unroll
            for (int nt = 0; nt < 4; nt++) {
                ldsm_x2t(bh[nt], sptr(&sb_h[brow * BP + wn + nt * 8]));
                ldsm_x2t(bl[nt], sptr(&sb_l[brow * BP + wn + nt * 8]));
            }
            uint32_t a[4][4];
            int arow = lane & 15;
            int acol = ks * 16 + (lane >> 4) * 8;
            #pragma unroll
            for (int mt = 0; mt < 4; mt++)
                ldsm_x4(a[mt], sptr(&sa_h[(wm + mt * 16 + arow) * AP + acol]));
            #pragma unroll
            for (int mt = 0; mt < 4; mt++)
                #pragma unroll
                for (int nt = 0; nt < 4; nt++) {
                    mma_bf16(acc[mt][nt], a[mt], bh[nt]);
                    mma_bf16(acc[mt][nt], a[mt], bl[nt]);
                }
            #pragma unroll
            for (int mt = 0; mt < 4; mt++)
                ldsm_x4(a[mt], sptr(&sa_l[(wm + mt * 16 + arow) * AP + acol]));
            #pragma unroll
            for (int mt = 0; mt < 4; mt++)
                #pragma unroll
                for (int nt = 0; nt < 4; nt++)
                    mma_bf16(acc[mt][nt], a[mt], bh[nt]);
        }
    }

    #pragma unroll
    for (int mt = 0; mt < 4; mt++)
        #pragma unroll
        for (int nt = 0; nt < 4; nt++) {
            int m = tm0 + wm + mt * 16 + (lane >> 2);
            int n = tn0 + wn + nt * 8 + (lane & 3) * 2;
            *(float2*)&Yb[(size_t)m * N + n]       = make_float2(acc[mt][nt][0], acc[mt][nt][1]);
            *(float2*)&Yb[(size_t)(m + 8) * N + n] = make_float2(acc[mt][nt][2], acc[mt][nt][3]);
        }
}

// wrappers: device-global pointers resolved in device code
__global__ void __launch_bounds__(256) gemm_qkv_kernel() {
    mma_gemm_body<QKV, CDIM>(g_wh, g_wl, g_xh, g_xl, g_qkv1);
}
__global__ void __launch_bounds__(256) gemm_out_kernel() {
    mma_gemm_body<CDIM, INNER>(g_owh, g_owl, g_ah, g_al, g_z);
}

// ---------------- depthwise 3x3, smem-tiled ---------------------------------
__global__ void dwconv3_kernel(const float* __restrict__ qwd,
                               const float* __restrict__ kwd,
                               const float* __restrict__ vwd) {
    __shared__ float s[10][WW + 2];
    int bc = blockIdx.y;              // b*QKV + c
    int c = bc % QKV;
    const float* wp = (c < 256) ? (qwd + c * 9)
                    : (c < 512) ? (kwd + (c - 256) * 9)
                                : (vwd + (c - 512) * 9);
    float w0 = wp[0], w1 = wp[1], w2 = wp[2];
    float w3 = wp[3], w4 = wp[4], w5 = wp[5];
    float w6 = wp[6], w7 = wp[7], w8 = wp[8];
    const float* ip = g_qkv1 + (size_t)bc * HW;
    int h0 = blockIdx.x * 8;
    int tx = threadIdx.x;  // 0..95
    int ty = threadIdx.y;  // 0..7
    #pragma unroll
    for (int r = ty; r < 10; r += 8) {
        int h = h0 - 1 + r;
        s[r][tx + 1] = (h >= 0 && h < HH) ? ip[h * WW + tx] : 0.f;
        if (tx == 0) { s[r][0] = 0.f; s[r][WW + 1] = 0.f; }
    }
    __syncthreads();
    float acc = w0 * s[ty][tx]     + w1 * s[ty][tx + 1]     + w2 * s[ty][tx + 2]
              + w3 * s[ty + 1][tx] + w4 * s[ty + 1][tx + 1] + w5 * s[ty + 1][tx + 2]
              + w6 * s[ty + 2][tx] + w7 * s[ty + 2][tx + 1] + w8 * s[ty + 2][tx + 2];
    g_qkv2[(size_t)bc * HW + (h0 + ty) * WW + tx] = acc;
}

// ---------------- k softmax stats -------------------------------------------
__global__ void kstats_kernel() {
    int bc = blockIdx.x;            // 0 .. BATCH*INNER-1
    int b = bc / INNER, c = bc % INNER;
    const float* kp = g_qkv2 + ((size_t)b * QKV + INNER + c) * HW;
    int t = threadIdx.x;
    __shared__ float sm[256];
    float m = -1e30f;
    for (int i = t; i < HW; i += 256) m = fmaxf(m, kp[i]);
    sm[t] = m; __syncthreads();
    for (int s = 128; s > 0; s >>= 1) { if (t < s) sm[t] = fmaxf(sm[t], sm[t + s]); __syncthreads(); }
    m = sm[0];
    __syncthreads();
    float sum = 0.f;
    for (int i = t; i < HW; i += 256) sum += __expf(kp[i] - m);
    sm[t] = sum; __syncthreads();
    for (int s = 128; s > 0; s >>= 1) { if (t < s) sm[t] += sm[t + s]; __syncthreads(); }
    if (t == 0) { g_kmax[bc] = m; g_krsum[bc] = 1.0f / sm[0]; }
}

// ---------------- context = softmax_k^T @ v, partial over n-chunks ----------
__global__ void context_part_kernel() {
    int bh = blockIdx.x;
    int chunk = blockIdx.y;          // 0..8, 1024 positions each
    int b = bh / HEADS, h = bh % HEADS;
    const float* kp = g_qkv2 + ((size_t)b * QKV + INNER + h * DH) * HW;
    const float* vp = g_qkv2 + ((size_t)b * QKV + 2 * INNER + h * DH) * HW;
    const float* km = g_kmax  + b * INNER + h * DH;
    const float* kr = g_krsum + b * INNER + h * DH;
    __shared__ float sk[DH][33];
    __shared__ float sv[DH][33];
    int t = threadIdx.x;             // 256
    int e = t & 31;
    int d0 = (t >> 5) * 4;
    float acc0 = 0.f, acc1 = 0.f, acc2 = 0.f, acc3 = 0.f;
    int nbeg = chunk * 1024, nend = nbeg + 1024;
    for (int n0 = nbeg; n0 < nend; n0 += 32) {
        #pragma unroll
        for (int i = 0; i < 4; i++) {
            int idx = t + i * 256;
            int d = idx >> 5, nn = idx & 31;
            float kv = kp[(size_t)d * HW + n0 + nn];
            sk[d][nn] = __expf(kv - km[d]) * kr[d];
            sv[d][nn] = vp[(size_t)d * HW + n0 + nn];
        }
        __syncthreads();
        #pragma unroll
        for (int nn = 0; nn < 32; nn++) {
            float vv = sv[e][nn];
            acc0 += sk[d0 + 0][nn] * vv;
            acc1 += sk[d0 + 1][nn] * vv;
            acc2 += sk[d0 + 2][nn] * vv;
            acc3 += sk[d0 + 3][nn] * vv;
        }
        __syncthreads();
    }
    float* cp = g_ctxp + ((size_t)chunk * BATCH * HEADS + bh) * DH * DH;
    cp[(d0 + 0) * DH + e] = acc0;
    cp[(d0 + 1) * DH + e] = acc1;
    cp[(d0 + 2) * DH + e] = acc2;
    cp[(d0 + 3) * DH + e] = acc3;
}
__global__ void context_reduce_kernel() {
    int bh = blockIdx.x;
    int i = threadIdx.x;             // 1024
    float s = 0.f;
    #pragma unroll
    for (int c = 0; c < 9; c++)
        s += g_ctxp[((size_t)c * BATCH * HEADS + bh) * DH * DH + i];
    g_ctx[(size_t)bh * DH * DH + i] = s;
}

// ---------------- q softmax @ context + silu -> split bf16 ------------------
__global__ void qattn_kernel() {
    int bh = blockIdx.y;
    int b = bh / HEADS, h = bh % HEADS;
    int n = blockIdx.x * 256 + threadIdx.x;
    __shared__ float sctx[DH][DH];
    for (int i = threadIdx.x; i < DH * DH; i += 256)
        sctx[i / DH][i % DH] = g_ctx[(size_t)bh * DH * DH + i];
    __syncthreads();
    const float* qp = g_qkv2 + ((size_t)b * QKV + h * DH) * HW + n;
    float qv[DH];
    float m = -1e30f;
    #pragma unroll
    for (int d = 0; d < DH; d++) { qv[d] = qp[(size_t)d * HW]; m = fmaxf(m, qv[d]); }
    float sum = 0.f;
    #pragma unroll
    for (int d = 0; d < DH; d++) { qv[d] = __expf(qv[d] - m); sum += qv[d]; }
    float sc = 0.17677669529663688f / sum;  // (1/sqrt(32)) / sum
    #pragma unroll
    for (int d = 0; d < DH; d++) qv[d] *= sc;
    size_t obase = ((size_t)b * INNER + h * DH) * HW + n;
    #pragma unroll
    for (int e = 0; e < DH; e++) {
        float o = 0.f;
        #pragma unroll
        for (int d = 0; d < DH; d++) o += qv[d] * sctx[d][e];
        o = o / (1.0f + __expf(-o));   // silu
        split_bf16(o, g_ah[obase + (size_t)e * HW], g_al[obase + (size_t)e * HW]);
    }
}

// ---------------- launch ----------------------------------------------------
extern "C" void kernel_launch(void* const* d_in, const int* in_sizes, int n_in,
                              void* d_out, int out_size) {
    const float* fmap       = (const float*)d_in[0];
    const float* norm_g     = (const float*)d_in[1];
    const float* q_w1       = (const float*)d_in[2];
    const float* q_wd       = (const float*)d_in[3];
    const float* k_w1       = (const float*)d_in[4];
    const float* k_wd       = (const float*)d_in[5];
    const float* v_w1       = (const float*)d_in[6];
    const float* v_wd       = (const float*)d_in[7];
    const float* out_w      = (const float*)d_in[8];
    const float* out_norm_g = (const float*)d_in[9];
    float* out = (float*)d_out;

    // GEMM smem: 3 stages * (2*128*40 + 2*32*136) halves * 2B = 113664
    const int GEMM_SMEM = 3 * (2 * 128 * 40 + 2 * 32 * 136) * 2;
    const int LN_SMEM = 512 * 33 * 4;   // 67584
    cudaFuncSetAttribute(gemm_qkv_kernel,
                         cudaFuncAttributeMaxDynamicSharedMemorySize, GEMM_SMEM);
    cudaFuncSetAttribute(gemm_out_kernel,
                         cudaFuncAttributeMaxDynamicSharedMemorySize, GEMM_SMEM);
    cudaFuncSetAttribute(ln_in_kernel,
                         cudaFuncAttributeMaxDynamicSharedMemorySize, LN_SMEM);
    cudaFuncSetAttribute(ln_out_kernel,
                         cudaFuncAttributeMaxDynamicSharedMemorySize, LN_SMEM);

    // bf16-pair weights
    convert_qkvw_kernel<<<(INNER * CDIM) / 256, 256>>>(q_w1, k_w1, v_w1);
    convert_outw_kernel<<<(CDIM * INNER) / 256, 256>>>(out_w);

    // input LN -> split bf16 planes (single pass)
    ln_in_kernel<<<(BATCH * HW) / 32, 256, LN_SMEM>>>(fmap, norm_g);

    // qkv = Wqkv @ xn  (tensor cores)
    gemm_qkv_kernel<<<dim3(HW / 128, QKV / 128, BATCH), 256, GEMM_SMEM>>>();

    // depthwise 3x3
    dwconv3_kernel<<<dim3(HH / 8, BATCH * QKV), dim3(96, 8)>>>(q_wd, k_wd, v_wd);

    // attention
    kstats_kernel<<<BATCH * INNER, 256>>>();
    context_part_kernel<<<dim3(BATCH * HEADS, 9), 256>>>();
    context_reduce_kernel<<<BATCH * HEADS, 1024>>>();
    qattn_kernel<<<dim3(HW / 256, BATCH * HEADS), 256>>>();

    // out projection (tensor cores)
    gemm_out_kernel<<<dim3(HW / 128, CDIM / 128, BATCH), 256, GEMM_SMEM>>>();

    // final LN (single pass)
    ln_out_kernel<<<(BATCH * HW) / 32, 256, LN_SMEM>>>(out_norm_g, out);
}

// round 7
// speedup vs baseline: 1.5342x; 1.1830x over previous
#include <cuda_runtime.h>
#include <cuda_bf16.h>
#include <cuda_fp16.h>
#include <math.h>
#include <stdint.h>

#define BATCH 8
#define CDIM  512
#define INNER 256
#define QKV   768
#define HEADS 8
#define DH    32
#define HH    96
#define WW    96
#define HW    9216   // 96*96

// ---------------- scratch (static device globals) ---------------------------
__device__ __half g_xf [(size_t)BATCH * CDIM  * HW];   // LN(x) fp16
__device__ float g_qkv1[(size_t)BATCH * QKV   * HW];   // after 1x1
__device__ float g_qkv2[(size_t)BATCH * QKV   * HW];   // after dwconv3
__device__ __half g_af [(size_t)BATCH * INNER * HW];   // attn+silu fp16
__device__ float g_z   [(size_t)BATCH * CDIM  * HW];   // after out conv1x1
__device__ __half g_wh [(size_t)QKV * CDIM];           // qkv weights hi
__device__ __half g_wl [(size_t)QKV * CDIM];           // qkv weights lo
__device__ __half g_owh[(size_t)CDIM * INNER];         // out weights hi
__device__ __half g_owl[(size_t)CDIM * INNER];         // out weights lo
__device__ float g_krsum[BATCH * INNER];
__device__ float g_ctx  [BATCH * HEADS * DH * DH];
__device__ float g_ctxp [(size_t)9 * BATCH * HEADS * DH * DH];

__device__ __forceinline__ void split_f16(float v, __half& h, __half& l) {
    h = __float2half(v);
    l = __float2half(v - __half2float(h));
}

// ---------------- weight conversion (fp16 hi/lo split) ----------------------
__global__ void convert_qkvw_kernel(const float* __restrict__ qw,
                                    const float* __restrict__ kw,
                                    const float* __restrict__ vw) {
    int i = blockIdx.x * blockDim.x + threadIdx.x;  // 0 .. INNER*CDIM-1
    split_f16(qw[i], g_wh[i], g_wl[i]);
    split_f16(kw[i], g_wh[i + INNER*CDIM], g_wl[i + INNER*CDIM]);
    split_f16(vw[i], g_wh[i + 2*INNER*CDIM], g_wl[i + 2*INNER*CDIM]);
}
__global__ void convert_outw_kernel(const float* __restrict__ ow) {
    int i = blockIdx.x * blockDim.x + threadIdx.x;  // 0 .. CDIM*INNER-1
    split_f16(ow[i], g_owh[i], g_owl[i]);
}

// ---------------- single-pass channel LNs (smem-buffered) -------------------
__global__ void ln_in_kernel(const float* __restrict__ x,
                             const float* __restrict__ g) {
    extern __shared__ float s[];            // [512][33]
    __shared__ float s_mean[32], s_r[32];
    int t = threadIdx.x;
    int pos0 = blockIdx.x * 32;
    int b = pos0 / HW;
    int hw0 = pos0 - b * HW;
    int lane = t & 31, crow = t >> 5;
    #pragma unroll 8
    for (int it = 0; it < 64; it++) {
        int c = crow + it * 8;
        s[c * 33 + lane] = x[((size_t)b * CDIM + c) * HW + hw0 + lane];
    }
    __syncthreads();
    int p = t >> 3, sub = t & 7;            // 8 threads per position
    float sm = 0.f, sq = 0.f;
    #pragma unroll 8
    for (int j = 0; j < 64; j++) {
        float v = s[(sub + j * 8) * 33 + p];
        sm += v; sq += v * v;
    }
    #pragma unroll
    for (int off = 4; off > 0; off >>= 1) {
        sm += __shfl_xor_sync(0xffffffffu, sm, off);
        sq += __shfl_xor_sync(0xffffffffu, sq, off);
    }
    float mean = sm * (1.f / CDIM);
    float var  = sq * (1.f / CDIM) - mean * mean;
    float r = rsqrtf(var + 1e-5f);
    if (sub == 0) { s_mean[p] = mean; s_r[p] = r; }
    __syncthreads();
    float m2 = s_mean[lane], r2 = s_r[lane];
    #pragma unroll 8
    for (int it = 0; it < 64; it++) {
        int c = crow + it * 8;
        float y = (s[c * 33 + lane] - m2) * r2 * g[c];
        g_xf[((size_t)b * CDIM + c) * HW + hw0 + lane] = __float2half(y);
    }
}

__global__ void ln_out_kernel(const float* __restrict__ g,
                              float* __restrict__ out) {
    extern __shared__ float s[];            // [512][33]
    __shared__ float s_mean[32], s_r[32];
    int t = threadIdx.x;
    int pos0 = blockIdx.x * 32;
    int b = pos0 / HW;
    int hw0 = pos0 - b * HW;
    int lane = t & 31, crow = t >> 5;
    #pragma unroll 8
    for (int it = 0; it < 64; it++) {
        int c = crow + it * 8;
        s[c * 33 + lane] = g_z[((size_t)b * CDIM + c) * HW + hw0 + lane];
    }
    __syncthreads();
    int p = t >> 3, sub = t & 7;
    float sm = 0.f, sq = 0.f;
    #pragma unroll 8
    for (int j = 0; j < 64; j++) {
        float v = s[(sub + j * 8) * 33 + p];
        sm += v; sq += v * v;
    }
    #pragma unroll
    for (int off = 4; off > 0; off >>= 1) {
        sm += __shfl_xor_sync(0xffffffffu, sm, off);
        sq += __shfl_xor_sync(0xffffffffu, sq, off);
    }
    float mean = sm * (1.f / CDIM);
    float var  = sq * (1.f / CDIM) - mean * mean;
    float r = rsqrtf(var + 1e-5f);
    if (sub == 0) { s_mean[p] = mean; s_r[p] = r; }
    __syncthreads();
    float m2 = s_mean[lane], r2 = s_r[lane];
    #pragma unroll 8
    for (int it = 0; it < 64; it++) {
        int c = crow + it * 8;
        out[((size_t)b * CDIM + c) * HW + hw0 + lane] =
            (s[c * 33 + lane] - m2) * r2 * g[c];
    }
}

// ---------------- tensor-core GEMM (fp16 2-term weight split) ---------------
// Y[b] = (Wh+Wl)[M,K] @ X[b][K,N], N = HW. Tile 128x128x32, 8 warps of 64x32.
__device__ __forceinline__ uint32_t sptr(const void* p) {
    return (uint32_t)__cvta_generic_to_shared(p);
}
__device__ __forceinline__ void cp_async16(void* sm, const void* gm) {
    asm volatile("cp.async.cg.shared.global [%0], [%1], 16;\n"
                 :: "r"(sptr(sm)), "l"(gm));
}
__device__ __forceinline__ void ldsm_x4(uint32_t* r, uint32_t a) {
    asm volatile("ldmatrix.sync.aligned.m8n8.x4.shared.b16 {%0,%1,%2,%3}, [%4];"
                 : "=r"(r[0]), "=r"(r[1]), "=r"(r[2]), "=r"(r[3]) : "r"(a));
}
__device__ __forceinline__ void ldsm_x2t(uint32_t* r, uint32_t a) {
    asm volatile("ldmatrix.sync.aligned.m8n8.x2.trans.shared.b16 {%0,%1}, [%2];"
                 : "=r"(r[0]), "=r"(r[1]) : "r"(a));
}
__device__ __forceinline__ void mma_f16(float* c, const uint32_t* a, const uint32_t* b) {
    asm volatile("mma.sync.aligned.m16n8k16.row.col.f32.f16.f16.f32 "
                 "{%0,%1,%2,%3},{%4,%5,%6,%7},{%8,%9},{%0,%1,%2,%3};"
                 : "+f"(c[0]), "+f"(c[1]), "+f"(c[2]), "+f"(c[3])
                 : "r"(a[0]), "r"(a[1]), "r"(a[2]), "r"(a[3]), "r"(b[0]), "r"(b[1]));
}

template<int M, int K>
__device__ __forceinline__ void mma_gemm_body(const __half* __restrict__ Wh,
                                              const __half* __restrict__ Wl,
                                              const __half* __restrict__ Xf,
                                              float* __restrict__ Y) {
    constexpr int N = HW;
    constexpr int BM = 128, BN = 128, BK = 32;
    constexpr int AP = BK + 8;      // 40 halves/row (80B): conflict-free ldsm
    constexpr int BP = BN + 8;      // 136 halves/row (272B)
    constexpr int A_SZ = BM * AP;   // 5120 halves/plane
    constexpr int B_SZ = BK * BP;   // 4352 halves
    constexpr int STAGE = 2 * A_SZ + B_SZ;   // 14592 halves = 29184 B
    constexpr int KC = K / BK;
    extern __shared__ __half smem[];

    int b = blockIdx.z;
    const __half* XfB = Xf + (size_t)b * K * N;
    float* Yb = Y + (size_t)b * M * N;
    int tm0 = blockIdx.y * BM;
    int tn0 = blockIdx.x * BN;
    int t = threadIdx.x;
    int lane = t & 31, warp = t >> 5;
    int wm = (warp & 1) * 64, wn = (warp >> 1) * 32;

    auto load_stage = [&](int kc, int s) {
        __half* sa_h = smem + (size_t)s * STAGE;
        __half* sa_l = sa_h + A_SZ;
        __half* sb   = sa_l + A_SZ;
        int k0 = kc * BK;
        #pragma unroll
        for (int i = 0; i < 2; i++) {
            int c = t + i * 256;
            int m  = c >> 2, kk = (c & 3) * 8;
            cp_async16(&sa_h[m * AP + kk], &Wh[(size_t)(tm0 + m) * K + k0 + kk]);
            cp_async16(&sa_l[m * AP + kk], &Wl[(size_t)(tm0 + m) * K + k0 + kk]);
            int kr = c >> 4, nn = (c & 15) * 8;
            cp_async16(&sb[kr * BP + nn], &XfB[(size_t)(k0 + kr) * N + tn0 + nn]);
        }
        asm volatile("cp.async.commit_group;");
    };

    float acc[4][4][4];
    #pragma unroll
    for (int i = 0; i < 4; i++)
        #pragma unroll
        for (int j = 0; j < 4; j++)
            #pragma unroll
            for (int r = 0; r < 4; r++) acc[i][j][r] = 0.f;

    load_stage(0, 0);
    load_stage(1, 1);
    for (int kc = 0; kc < KC; kc++) {
        int s = kc % 3;
        if (kc + 1 < KC) asm volatile("cp.async.wait_group 1;");
        else             asm volatile("cp.async.wait_group 0;");
        __syncthreads();
        if (kc + 2 < KC) load_stage(kc + 2, (kc + 2) % 3);

        __half* sa_h = smem + (size_t)s * STAGE;
        __half* sa_l = sa_h + A_SZ;
        __half* sb   = sa_l + A_SZ;

        #pragma unroll
        for (int ks = 0; ks < 2; ks++) {
            uint32_t bx[4][2];
            int brow = ks * 16 + (lane & 15);
            #pragma unroll
            for (int nt = 0; nt < 4; nt++)
                ldsm_x2t(bx[nt], sptr(&sb[brow * BP + wn + nt * 8]));
            uint32_t a[4][4];
            int arow = lane & 15;
            int acol = ks * 16 + (lane >> 4) * 8;
            #pragma unroll
            for (int mt = 0; mt < 4; mt++)
                ldsm_x4(a[mt], sptr(&sa_h[(wm + mt * 16 + arow) * AP + acol]));
            #pragma unroll
            for (int mt = 0; mt < 4; mt++)
                #pragma unroll
                for (int nt = 0; nt < 4; nt++)
                    mma_f16(acc[mt][nt], a[mt], bx[nt]);
            #pragma unroll
            for (int mt = 0; mt < 4; mt++)
                ldsm_x4(a[mt], sptr(&sa_l[(wm + mt * 16 + arow) * AP + acol]));
            #pragma unroll
            for (int mt = 0; mt < 4; mt++)
                #pragma unroll
                for (int nt = 0; nt < 4; nt++)
                    mma_f16(acc[mt][nt], a[mt], bx[nt]);
        }
    }

    #pragma unroll
    for (int mt = 0; mt < 4; mt++)
        #pragma unroll
        for (int nt = 0; nt < 4; nt++) {
            int m = tm0 + wm + mt * 16 + (lane >> 2);
            int n = tn0 + wn + nt * 8 + (lane & 3) * 2;
            *(float2*)&Yb[(size_t)m * N + n]       = make_float2(acc[mt][nt][0], acc[mt][nt][1]);
            *(float2*)&Yb[(size_t)(m + 8) * N + n] = make_float2(acc[mt][nt][2], acc[mt][nt][3]);
        }
}

// wrappers: device-global pointers resolved in device code
__global__ void __launch_bounds__(256) gemm_qkv_kernel() {
    mma_gemm_body<QKV, CDIM>(g_wh, g_wl, g_xf, g_qkv1);
}
__global__ void __launch_bounds__(256) gemm_out_kernel() {
    mma_gemm_body<CDIM, INNER>(g_owh, g_owl, g_af, g_z);
}

// ---------------- depthwise 3x3, smem-tiled ---------------------------------
__global__ void dwconv3_kernel(const float* __restrict__ qwd,
                               const float* __restrict__ kwd,
                               const float* __restrict__ vwd) {
    __shared__ float s[10][WW + 2];
    int bc = blockIdx.y;              // b*QKV + c
    int c = bc % QKV;
    const float* wp = (c < 256) ? (qwd + c * 9)
                    : (c < 512) ? (kwd + (c - 256) * 9)
                                : (vwd + (c - 512) * 9);
    float w0 = wp[0], w1 = wp[1], w2 = wp[2];
    float w3 = wp[3], w4 = wp[4], w5 = wp[5];
    float w6 = wp[6], w7 = wp[7], w8 = wp[8];
    const float* ip = g_qkv1 + (size_t)bc * HW;
    int h0 = blockIdx.x * 8;
    int tx = threadIdx.x;  // 0..95
    int ty = threadIdx.y;  // 0..7
    #pragma unroll
    for (int r = ty; r < 10; r += 8) {
        int h = h0 - 1 + r;
        s[r][tx + 1] = (h >= 0 && h < HH) ? ip[h * WW + tx] : 0.f;
        if (tx == 0) { s[r][0] = 0.f; s[r][WW + 1] = 0.f; }
    }
    __syncthreads();
    float acc = w0 * s[ty][tx]     + w1 * s[ty][tx + 1]     + w2 * s[ty][tx + 2]
              + w3 * s[ty + 1][tx] + w4 * s[ty + 1][tx + 1] + w5 * s[ty + 1][tx + 2]
              + w6 * s[ty + 2][tx] + w7 * s[ty + 2][tx + 1] + w8 * s[ty + 2][tx + 2];
    g_qkv2[(size_t)bc * HW + (h0 + ty) * WW + tx] = acc;
}

// ---------------- k softmax: single pass sum(exp) (values tiny; no max) -----
__global__ void kstats_kernel() {
    int bc = blockIdx.x;            // 0 .. BATCH*INNER-1
    int b = bc / INNER, c = bc % INNER;
    const float* kp = g_qkv2 + ((size_t)b * QKV + INNER + c) * HW;
    int t = threadIdx.x;
    __shared__ float sm[256];
    float sum = 0.f;
    for (int i = t; i < HW; i += 256) sum += __expf(kp[i]);
    sm[t] = sum; __syncthreads();
    for (int s = 128; s > 0; s >>= 1) { if (t < s) sm[t] += sm[t + s]; __syncthreads(); }
    if (t == 0) g_krsum[bc] = 1.0f / sm[0];
}

// ---------------- context = softmax_k^T @ v, partial over n-chunks ----------
__global__ void context_part_kernel() {
    int bh = blockIdx.x;
    int chunk = blockIdx.y;          // 0..8, 1024 positions each
    int b = bh / HEADS, h = bh % HEADS;
    const float* kp = g_qkv2 + ((size_t)b * QKV + INNER + h * DH) * HW;
    const float* vp = g_qkv2 + ((size_t)b * QKV + 2 * INNER + h * DH) * HW;
    const float* kr = g_krsum + b * INNER + h * DH;
    __shared__ float sk[DH][33];
    __shared__ float sv[DH][33];
    int t = threadIdx.x;             // 256
    int e = t & 31;
    int d0 = (t >> 5) * 4;
    float acc0 = 0.f, acc1 = 0.f, acc2 = 0.f, acc3 = 0.f;
    int nbeg = chunk * 1024, nend = nbeg + 1024;
    for (int n0 = nbeg; n0 < nend; n0 += 32) {
        #pragma unroll
        for (int i = 0; i < 4; i++) {
            int idx = t + i * 256;
            int d = idx >> 5, nn = idx & 31;
            float kv = kp[(size_t)d * HW + n0 + nn];
            sk[d][nn] = __expf(kv) * kr[d];
            sv[d][nn] = vp[(size_t)d * HW + n0 + nn];
        }
        __syncthreads();
        #pragma unroll
        for (int nn = 0; nn < 32; nn++) {
            float vv = sv[e][nn];
            acc0 += sk[d0 + 0][nn] * vv;
            acc1 += sk[d0 + 1][nn] * vv;
            acc2 += sk[d0 + 2][nn] * vv;
            acc3 += sk[d0 + 3][nn] * vv;
        }
        __syncthreads();
    }
    float* cp = g_ctxp + ((size_t)chunk * BATCH * HEADS + bh) * DH * DH;
    cp[(d0 + 0) * DH + e] = acc0;
    cp[(d0 + 1) * DH + e] = acc1;
    cp[(d0 + 2) * DH + e] = acc2;
    cp[(d0 + 3) * DH + e] = acc3;
}
__global__ void context_reduce_kernel() {
    int bh = blockIdx.x;
    int i = threadIdx.x;             // 1024
    float s = 0.f;
    #pragma unroll
    for (int c = 0; c < 9; c++)
        s += g_ctxp[((size_t)c * BATCH * HEADS + bh) * DH * DH + i];
    g_ctx[(size_t)bh * DH * DH + i] = s;
}

// ---------------- q softmax @ context + silu -> fp16 ------------------------
__global__ void qattn_kernel() {
    int bh = blockIdx.y;
    int b = bh / HEADS, h = bh % HEADS;
    int n = blockIdx.x * 256 + threadIdx.x;
    __shared__ float sctx[DH][DH];
    for (int i = threadIdx.x; i < DH * DH; i += 256)
        sctx[i / DH][i % DH] = g_ctx[(size_t)bh * DH * DH + i];
    __syncthreads();
    const float* qp = g_qkv2 + ((size_t)b * QKV + h * DH) * HW + n;
    float qv[DH];
    float m = -1e30f;
    #pragma unroll
    for (int d = 0; d < DH; d++) { qv[d] = qp[(size_t)d * HW]; m = fmaxf(m, qv[d]); }
    float sum = 0.f;
    #pragma unroll
    for (int d = 0; d < DH; d++) { qv[d] = __expf(qv[d] - m); sum += qv[d]; }
    float sc = 0.17677669529663688f / sum;  // (1/sqrt(32)) / sum
    #pragma unroll
    for (int d = 0; d < DH; d++) qv[d] *= sc;
    size_t obase = ((size_t)b * INNER + h * DH) * HW + n;
    #pragma unroll
    for (int e = 0; e < DH; e++) {
        float o = 0.f;
        #pragma unroll
        for (int d = 0; d < DH; d++) o += qv[d] * sctx[d][e];
        o = o / (1.0f + __expf(-o));   // silu
        g_af[obase + (size_t)e * HW] = __float2half(o);
    }
}

// ---------------- launch ----------------------------------------------------
extern "C" void kernel_launch(void* const* d_in, const int* in_sizes, int n_in,
                              void* d_out, int out_size) {
    const float* fmap       = (const float*)d_in[0];
    const float* norm_g     = (const float*)d_in[1];
    const float* q_w1       = (const float*)d_in[2];
    const float* q_wd       = (const float*)d_in[3];
    const float* k_w1       = (const float*)d_in[4];
    const float* k_wd       = (const float*)d_in[5];
    const float* v_w1       = (const float*)d_in[6];
    const float* v_wd       = (const float*)d_in[7];
    const float* out_w      = (const float*)d_in[8];
    const float* out_norm_g = (const float*)d_in[9];
    float* out = (float*)d_out;

    // GEMM smem: 3 stages * (2*128*40 + 32*136) halves * 2B = 87552
    const int GEMM_SMEM = 3 * (2 * 128 * 40 + 32 * 136) * 2;
    const int LN_SMEM = 512 * 33 * 4;   // 67584
    cudaFuncSetAttribute(gemm_qkv_kernel,
                         cudaFuncAttributeMaxDynamicSharedMemorySize, GEMM_SMEM);
    cudaFuncSetAttribute(gemm_out_kernel,
                         cudaFuncAttributeMaxDynamicSharedMemorySize, GEMM_SMEM);
    cudaFuncSetAttribute(ln_in_kernel,
                         cudaFuncAttributeMaxDynamicSharedMemorySize, LN_SMEM);
    cudaFuncSetAttribute(ln_out_kernel,
                         cudaFuncAttributeMaxDynamicSharedMemorySize, LN_SMEM);

    // fp16-pair weights
    convert_qkvw_kernel<<<(INNER * CDIM) / 256, 256>>>(q_w1, k_w1, v_w1);
    convert_outw_kernel<<<(CDIM * INNER) / 256, 256>>>(out_w);

    // input LN -> fp16 plane (single pass)
    ln_in_kernel<<<(BATCH * HW) / 32, 256, LN_SMEM>>>(fmap, norm_g);

    // qkv = Wqkv @ xn  (tensor cores)
    gemm_qkv_kernel<<<dim3(HW / 128, QKV / 128, BATCH), 256, GEMM_SMEM>>>();

    // depthwise 3x3
    dwconv3_kernel<<<dim3(HH / 8, BATCH * QKV), dim3(96, 8)>>>(q_wd, k_wd, v_wd);

    // attention
    kstats_kernel<<<BATCH * INNER, 256>>>();
    context_part_kernel<<<dim3(BATCH * HEADS, 9), 256>>>();
    context_reduce_kernel<<<BATCH * HEADS, 1024>>>();
    qattn_kernel<<<dim3(HW / 256, BATCH * HEADS), 256>>>();

    // out projection (tensor cores)
    gemm_out_kernel<<<dim3(HW / 128, CDIM / 128, BATCH), 256, GEMM_SMEM>>>();

    // final LN (single pass)
    ln_out_kernel<<<(BATCH * HW) / 32, 256, LN_SMEM>>>(out_norm_g, out);
}

// round 8
// speedup vs baseline: 1.8518x; 1.2070x over previous
#include <cuda_runtime.h>
#include <cuda_bf16.h>
#include <cuda_fp16.h>
#include <math.h>
#include <stdint.h>

#define BATCH 8
#define CDIM  512
#define INNER 256
#define QKV   768
#define HEADS 8
#define DH    32
#define HH    96
#define WW    96
#define HW    9216   // 96*96

// ---------------- scratch (static device globals) ---------------------------
__device__ __half g_xf [(size_t)BATCH * CDIM  * HW];   // LN(x) fp16
__device__ float g_qkv1[(size_t)BATCH * QKV   * HW];   // after 1x1
__device__ float g_qkv2[(size_t)BATCH * QKV   * HW];   // after dwconv3
__device__ __half g_af [(size_t)BATCH * INNER * HW];   // attn+silu fp16
__device__ float g_z   [(size_t)BATCH * CDIM  * HW];   // after out conv1x1
__device__ __half g_wh [(size_t)QKV * CDIM];           // qkv weights hi
__device__ __half g_wl [(size_t)QKV * CDIM];           // qkv weights lo
__device__ __half g_owh[(size_t)CDIM * INNER];         // out weights hi
__device__ __half g_owl[(size_t)CDIM * INNER];         // out weights lo
__device__ float g_krsum[BATCH * INNER];
__device__ float g_ctx  [BATCH * HEADS * DH * DH];
__device__ float g_ctxp [(size_t)9 * BATCH * HEADS * DH * DH];

__device__ __forceinline__ void split_f16(float v, __half& h, __half& l) {
    h = __float2half(v);
    l = __float2half(v - __half2float(h));
}

// ---------------- merged weight conversion (all four splits, same range) ----
__global__ void convert_w_kernel(const float* __restrict__ qw,
                                 const float* __restrict__ kw,
                                 const float* __restrict__ vw,
                                 const float* __restrict__ ow) {
    int i = blockIdx.x * blockDim.x + threadIdx.x;  // 0 .. INNER*CDIM-1
    split_f16(qw[i], g_wh[i], g_wl[i]);
    split_f16(kw[i], g_wh[i + INNER*CDIM], g_wl[i + INNER*CDIM]);
    split_f16(vw[i], g_wh[i + 2*INNER*CDIM], g_wl[i + 2*INNER*CDIM]);
    split_f16(ow[i], g_owh[i], g_owl[i]);              // CDIM*INNER == INNER*CDIM
}

// ---------------- single-pass channel LNs (smem-buffered) -------------------
__global__ void ln_in_kernel(const float* __restrict__ x,
                             const float* __restrict__ g) {
    extern __shared__ float s[];            // [512][33]
    __shared__ float s_mean[32], s_r[32];
    int t = threadIdx.x;
    int pos0 = blockIdx.x * 32;
    int b = pos0 / HW;
    int hw0 = pos0 - b * HW;
    int lane = t & 31, crow = t >> 5;
    #pragma unroll 8
    for (int it = 0; it < 64; it++) {
        int c = crow + it * 8;
        s[c * 33 + lane] = x[((size_t)b * CDIM + c) * HW + hw0 + lane];
    }
    __syncthreads();
    int p = t >> 3, sub = t & 7;            // 8 threads per position
    float sm = 0.f, sq = 0.f;
    #pragma unroll 8
    for (int j = 0; j < 64; j++) {
        float v = s[(sub + j * 8) * 33 + p];
        sm += v; sq += v * v;
    }
    #pragma unroll
    for (int off = 4; off > 0; off >>= 1) {
        sm += __shfl_xor_sync(0xffffffffu, sm, off);
        sq += __shfl_xor_sync(0xffffffffu, sq, off);
    }
    float mean = sm * (1.f / CDIM);
    float var  = sq * (1.f / CDIM) - mean * mean;
    float r = rsqrtf(var + 1e-5f);
    if (sub == 0) { s_mean[p] = mean; s_r[p] = r; }
    __syncthreads();
    float m2 = s_mean[lane], r2 = s_r[lane];
    #pragma unroll 8
    for (int it = 0; it < 64; it++) {
        int c = crow + it * 8;
        float y = (s[c * 33 + lane] - m2) * r2 * g[c];
        g_xf[((size_t)b * CDIM + c) * HW + hw0 + lane] = __float2half(y);
    }
}

__global__ void ln_out_kernel(const float* __restrict__ g,
                              float* __restrict__ out) {
    extern __shared__ float s[];            // [512][33]
    __shared__ float s_mean[32], s_r[32];
    int t = threadIdx.x;
    int pos0 = blockIdx.x * 32;
    int b = pos0 / HW;
    int hw0 = pos0 - b * HW;
    int lane = t & 31, crow = t >> 5;
    #pragma unroll 8
    for (int it = 0; it < 64; it++) {
        int c = crow + it * 8;
        s[c * 33 + lane] = g_z[((size_t)b * CDIM + c) * HW + hw0 + lane];
    }
    __syncthreads();
    int p = t >> 3, sub = t & 7;
    float sm = 0.f, sq = 0.f;
    #pragma unroll 8
    for (int j = 0; j < 64; j++) {
        float v = s[(sub + j * 8) * 33 + p];
        sm += v; sq += v * v;
    }
    #pragma unroll
    for (int off = 4; off > 0; off >>= 1) {
        sm += __shfl_xor_sync(0xffffffffu, sm, off);
        sq += __shfl_xor_sync(0xffffffffu, sq, off);
    }
    float mean = sm * (1.f / CDIM);
    float var  = sq * (1.f / CDIM) - mean * mean;
    float r = rsqrtf(var + 1e-5f);
    if (sub == 0) { s_mean[p] = mean; s_r[p] = r; }
    __syncthreads();
    float m2 = s_mean[lane], r2 = s_r[lane];
    #pragma unroll 8
    for (int it = 0; it < 64; it++) {
        int c = crow + it * 8;
        out[((size_t)b * CDIM + c) * HW + hw0 + lane] =
            (s[c * 33 + lane] - m2) * r2 * g[c];
    }
}

// ---------------- tensor-core GEMM (fp16 2-term weight split, BK=64) --------
// Y[b] = (Wh+Wl)[M,K] @ X[b][K,N], N = HW. Tile 128x128x64, 8 warps of 64x32.
__device__ __forceinline__ uint32_t sptr(const void* p) {
    return (uint32_t)__cvta_generic_to_shared(p);
}
__device__ __forceinline__ void cp_async16(void* sm, const void* gm) {
    asm volatile("cp.async.cg.shared.global [%0], [%1], 16;\n"
                 :: "r"(sptr(sm)), "l"(gm));
}
__device__ __forceinline__ void ldsm_x4(uint32_t* r, uint32_t a) {
    asm volatile("ldmatrix.sync.aligned.m8n8.x4.shared.b16 {%0,%1,%2,%3}, [%4];"
                 : "=r"(r[0]), "=r"(r[1]), "=r"(r[2]), "=r"(r[3]) : "r"(a));
}
__device__ __forceinline__ void ldsm_x2t(uint32_t* r, uint32_t a) {
    asm volatile("ldmatrix.sync.aligned.m8n8.x2.trans.shared.b16 {%0,%1}, [%2];"
                 : "=r"(r[0]), "=r"(r[1]) : "r"(a));
}
__device__ __forceinline__ void mma_f16(float* c, const uint32_t* a, const uint32_t* b) {
    asm volatile("mma.sync.aligned.m16n8k16.row.col.f32.f16.f16.f32 "
                 "{%0,%1,%2,%3},{%4,%5,%6,%7},{%8,%9},{%0,%1,%2,%3};"
                 : "+f"(c[0]), "+f"(c[1]), "+f"(c[2]), "+f"(c[3])
                 : "r"(a[0]), "r"(a[1]), "r"(a[2]), "r"(a[3]), "r"(b[0]), "r"(b[1]));
}

template<int M, int K>
__device__ __forceinline__ void mma_gemm_body(const __half* __restrict__ Wh,
                                              const __half* __restrict__ Wl,
                                              const __half* __restrict__ Xf,
                                              float* __restrict__ Y) {
    constexpr int N = HW;
    constexpr int BM = 128, BN = 128, BK = 64;
    constexpr int AP = BK + 8;      // 72 halves/row (144B): conflict-free ldsm
    constexpr int BP = BN + 8;      // 136 halves/row (272B)
    constexpr int A_SZ = BM * AP;   // 9216 halves/plane
    constexpr int B_SZ = BK * BP;   // 8704 halves
    constexpr int STAGE = 2 * A_SZ + B_SZ;   // 27136 halves = 54272 B
    constexpr int KC = K / BK;
    extern __shared__ __half smem[];

    int b = blockIdx.z;
    const __half* XfB = Xf + (size_t)b * K * N;
    float* Yb = Y + (size_t)b * M * N;
    int tm0 = blockIdx.y * BM;
    int tn0 = blockIdx.x * BN;
    int t = threadIdx.x;
    int lane = t & 31, warp = t >> 5;
    int wm = (warp & 1) * 64, wn = (warp >> 1) * 32;

    auto load_stage = [&](int kc, int s) {
        __half* sa_h = smem + (size_t)s * STAGE;
        __half* sa_l = sa_h + A_SZ;
        __half* sb   = sa_l + A_SZ;
        int k0 = kc * BK;
        #pragma unroll
        for (int i = 0; i < 4; i++) {
            int c = t + i * 256;            // 0..1023
            int m  = c >> 3, kk = (c & 7) * 8;
            cp_async16(&sa_h[m * AP + kk], &Wh[(size_t)(tm0 + m) * K + k0 + kk]);
            cp_async16(&sa_l[m * AP + kk], &Wl[(size_t)(tm0 + m) * K + k0 + kk]);
            int kr = c >> 4, nn = (c & 15) * 8;
            cp_async16(&sb[kr * BP + nn], &XfB[(size_t)(k0 + kr) * N + tn0 + nn]);
        }
        asm volatile("cp.async.commit_group;");
    };

    float acc[4][4][4];
    #pragma unroll
    for (int i = 0; i < 4; i++)
        #pragma unroll
        for (int j = 0; j < 4; j++)
            #pragma unroll
            for (int r = 0; r < 4; r++) acc[i][j][r] = 0.f;

    load_stage(0, 0);
    for (int kc = 0; kc < KC; kc++) {
        int s = kc & 1;
        asm volatile("cp.async.wait_group 0;");
        __syncthreads();
        if (kc + 1 < KC) load_stage(kc + 1, s ^ 1);

        __half* sa_h = smem + (size_t)s * STAGE;
        __half* sa_l = sa_h + A_SZ;
        __half* sb   = sa_l + A_SZ;

        #pragma unroll
        for (int ks = 0; ks < 4; ks++) {
            uint32_t bx[4][2];
            int brow = ks * 16 + (lane & 15);
            #pragma unroll
            for (int nt = 0; nt < 4; nt++)
                ldsm_x2t(bx[nt], sptr(&sb[brow * BP + wn + nt * 8]));
            uint32_t a[4][4];
            int arow = lane & 15;
            int acol = ks * 16 + (lane >> 4) * 8;
            #pragma unroll
            for (int mt = 0; mt < 4; mt++)
                ldsm_x4(a[mt], sptr(&sa_h[(wm + mt * 16 + arow) * AP + acol]));
            #pragma unroll
            for (int mt = 0; mt < 4; mt++)
                #pragma unroll
                for (int nt = 0; nt < 4; nt++)
                    mma_f16(acc[mt][nt], a[mt], bx[nt]);
            #pragma unroll
            for (int mt = 0; mt < 4; mt++)
                ldsm_x4(a[mt], sptr(&sa_l[(wm + mt * 16 + arow) * AP + acol]));
            #pragma unroll
            for (int mt = 0; mt < 4; mt++)
                #pragma unroll
                for (int nt = 0; nt < 4; nt++)
                    mma_f16(acc[mt][nt], a[mt], bx[nt]);
        }
    }

    #pragma unroll
    for (int mt = 0; mt < 4; mt++)
        #pragma unroll
        for (int nt = 0; nt < 4; nt++) {
            int m = tm0 + wm + mt * 16 + (lane >> 2);
            int n = tn0 + wn + nt * 8 + (lane & 3) * 2;
            *(float2*)&Yb[(size_t)m * N + n]       = make_float2(acc[mt][nt][0], acc[mt][nt][1]);
            *(float2*)&Yb[(size_t)(m + 8) * N + n] = make_float2(acc[mt][nt][2], acc[mt][nt][3]);
        }
}

// wrappers: device-global pointers resolved in device code
__global__ void __launch_bounds__(256) gemm_qkv_kernel() {
    mma_gemm_body<QKV, CDIM>(g_wh, g_wl, g_xf, g_qkv1);
}
__global__ void __launch_bounds__(256) gemm_out_kernel() {
    mma_gemm_body<CDIM, INNER>(g_owh, g_owl, g_af, g_z);
}

// ---------------- depthwise 3x3, full-image smem ----------------------------
__global__ void dwconv3_kernel(const float* __restrict__ qwd,
                               const float* __restrict__ kwd,
                               const float* __restrict__ vwd) {
    __shared__ float s[98][100];
    int bc = blockIdx.x;              // b*QKV + c
    int c = bc % QKV;
    const float* wp = (c < 256) ? (qwd + c * 9)
                    : (c < 512) ? (kwd + (c - 256) * 9)
                                : (vwd + (c - 512) * 9);
    float w0 = wp[0], w1 = wp[1], w2 = wp[2];
    float w3 = wp[3], w4 = wp[4], w5 = wp[5];
    float w6 = wp[6], w7 = wp[7], w8 = wp[8];
    const float* ip = g_qkv1 + (size_t)bc * HW;
    int tx = threadIdx.x;  // 0..95
    int ty = threadIdx.y;  // 0..7
    for (int r = ty; r < 98; r += 8) {
        int hr = r - 1;
        s[r][tx + 1] = (hr >= 0 && hr < HH) ? ip[hr * WW + tx] : 0.f;
        if (tx == 0)  s[r][0]  = 0.f;
        if (tx == 95) s[r][97] = 0.f;
    }
    __syncthreads();
    float* op = g_qkv2 + (size_t)bc * HW;
    #pragma unroll
    for (int g = 0; g < 12; g++) {
        int h = g * 8 + ty;
        float acc = w0 * s[h][tx]     + w1 * s[h][tx + 1]     + w2 * s[h][tx + 2]
                  + w3 * s[h + 1][tx] + w4 * s[h + 1][tx + 1] + w5 * s[h + 1][tx + 2]
                  + w6 * s[h + 2][tx] + w7 * s[h + 2][tx + 1] + w8 * s[h + 2][tx + 2];
        op[h * WW + tx] = acc;
    }
}

// ---------------- k softmax: single pass sum(exp) (values tiny; no max) -----
__global__ void kstats_kernel() {
    int bc = blockIdx.x;            // 0 .. BATCH*INNER-1
    int b = bc / INNER, c = bc % INNER;
    const float* kp = g_qkv2 + ((size_t)b * QKV + INNER + c) * HW;
    int t = threadIdx.x;
    __shared__ float sm[256];
    float sum = 0.f;
    for (int i = t; i < HW; i += 256) sum += __expf(kp[i]);
    sm[t] = sum; __syncthreads();
    for (int s = 128; s > 0; s >>= 1) { if (t < s) sm[t] += sm[t + s]; __syncthreads(); }
    if (t == 0) g_krsum[bc] = 1.0f / sm[0];
}

// ---------------- context = softmax_k^T @ v, partial over n-chunks ----------
__global__ void context_part_kernel() {
    int bh = blockIdx.x;
    int chunk = blockIdx.y;          // 0..8, 1024 positions each
    int b = bh / HEADS, h = bh % HEADS;
    const float* kp = g_qkv2 + ((size_t)b * QKV + INNER + h * DH) * HW;
    const float* vp = g_qkv2 + ((size_t)b * QKV + 2 * INNER + h * DH) * HW;
    const float* kr = g_krsum + b * INNER + h * DH;
    __shared__ float sk[DH][33];
    __shared__ float sv[DH][33];
    int t = threadIdx.x;             // 256
    int e = t & 31;
    int d0 = (t >> 5) * 4;
    float acc0 = 0.f, acc1 = 0.f, acc2 = 0.f, acc3 = 0.f;
    int nbeg = chunk * 1024, nend = nbeg + 1024;
    for (int n0 = nbeg; n0 < nend; n0 += 32) {
        #pragma unroll
        for (int i = 0; i < 4; i++) {
            int idx = t + i * 256;
            int d = idx >> 5, nn = idx & 31;
            float kv = kp[(size_t)d * HW + n0 + nn];
            sk[d][nn] = __expf(kv) * kr[d];
            sv[d][nn] = vp[(size_t)d * HW + n0 + nn];
        }
        __syncthreads();
        #pragma unroll
        for (int nn = 0; nn < 32; nn++) {
            float vv = sv[e][nn];
            acc0 += sk[d0 + 0][nn] * vv;
            acc1 += sk[d0 + 1][nn] * vv;
            acc2 += sk[d0 + 2][nn] * vv;
            acc3 += sk[d0 + 3][nn] * vv;
        }
        __syncthreads();
    }
    float* cp = g_ctxp + ((size_t)chunk * BATCH * HEADS + bh) * DH * DH;
    cp[(d0 + 0) * DH + e] = acc0;
    cp[(d0 + 1) * DH + e] = acc1;
    cp[(d0 + 2) * DH + e] = acc2;
    cp[(d0 + 3) * DH + e] = acc3;
}
__global__ void context_reduce_kernel() {
    int bh = blockIdx.x;
    int i = threadIdx.x;             // 1024
    float s = 0.f;
    #pragma unroll
    for (int c = 0; c < 9; c++)
        s += g_ctxp[((size_t)c * BATCH * HEADS + bh) * DH * DH + i];
    g_ctx[(size_t)bh * DH * DH + i] = s;
}

// ---------------- q softmax @ context + silu -> fp16 ------------------------
__global__ void qattn_kernel() {
    int bh = blockIdx.y;
    int b = bh / HEADS, h = bh % HEADS;
    int n = blockIdx.x * 256 + threadIdx.x;
    __shared__ float sctx[DH][DH];
    for (int i = threadIdx.x; i < DH * DH; i += 256)
        sctx[i / DH][i % DH] = g_ctx[(size_t)bh * DH * DH + i];
    __syncthreads();
    const float* qp = g_qkv2 + ((size_t)b * QKV + h * DH) * HW + n;
    float qv[DH];
    float m = -1e30f;
    #pragma unroll
    for (int d = 0; d < DH; d++) { qv[d] = qp[(size_t)d * HW]; m = fmaxf(m, qv[d]); }
    float sum = 0.f;
    #pragma unroll
    for (int d = 0; d < DH; d++) { qv[d] = __expf(qv[d] - m); sum += qv[d]; }
    float sc = 0.17677669529663688f / sum;  // (1/sqrt(32)) / sum
    #pragma unroll
    for (int d = 0; d < DH; d++) qv[d] *= sc;
    size_t obase = ((size_t)b * INNER + h * DH) * HW + n;
    #pragma unroll
    for (int e = 0; e < DH; e++) {
        float o = 0.f;
        #pragma unroll
        for (int d = 0; d < DH; d++) o += qv[d] * sctx[d][e];
        o = o / (1.0f + __expf(-o));   // silu
        g_af[obase + (size_t)e * HW] = __float2half(o);
    }
}

// ---------------- launch ----------------------------------------------------
extern "C" void kernel_launch(void* const* d_in, const int* in_sizes, int n_in,
                              void* d_out, int out_size) {
    const float* fmap       = (const float*)d_in[0];
    const float* norm_g     = (const float*)d_in[1];
    const float* q_w1       = (const float*)d_in[2];
    const float* q_wd       = (const float*)d_in[3];
    const float* k_w1       = (const float*)d_in[4];
    const float* k_wd       = (const float*)d_in[5];
    const float* v_w1       = (const float*)d_in[6];
    const float* v_wd       = (const float*)d_in[7];
    const float* out_w      = (const float*)d_in[8];
    const float* out_norm_g = (const float*)d_in[9];
    float* out = (float*)d_out;

    // GEMM smem: 2 stages * (2*128*72 + 64*136) halves * 2B = 108544
    const int GEMM_SMEM = 2 * (2 * 128 * 72 + 64 * 136) * 2;
    const int LN_SMEM = 512 * 33 * 4;   // 67584
    cudaFuncSetAttribute(gemm_qkv_kernel,
                         cudaFuncAttributeMaxDynamicSharedMemorySize, GEMM_SMEM);
    cudaFuncSetAttribute(gemm_out_kernel,
                         cudaFuncAttributeMaxDynamicSharedMemorySize, GEMM_SMEM);
    cudaFuncSetAttribute(ln_in_kernel,
                         cudaFuncAttributeMaxDynamicSharedMemorySize, LN_SMEM);
    cudaFuncSetAttribute(ln_out_kernel,
                         cudaFuncAttributeMaxDynamicSharedMemorySize, LN_SMEM);

    // fp16-pair weights (all four tensors, one kernel)
    convert_w_kernel<<<(INNER * CDIM) / 256, 256>>>(q_w1, k_w1, v_w1, out_w);

    // input LN -> fp16 plane (single pass)
    ln_in_kernel<<<(BATCH * HW) / 32, 256, LN_SMEM>>>(fmap, norm_g);

    // qkv = Wqkv @ xn  (tensor cores)
    gemm_qkv_kernel<<<dim3(HW / 128, QKV / 128, BATCH), 256, GEMM_SMEM>>>();

    // depthwise 3x3 (full image per block)
    dwconv3_kernel<<<BATCH * QKV, dim3(96, 8)>>>(q_wd, k_wd, v_wd);

    // attention
    kstats_kernel<<<BATCH * INNER, 256>>>();
    context_part_kernel<<<dim3(BATCH * HEADS, 9), 256>>>();
    context_reduce_kernel<<<BATCH * HEADS, 1024>>>();
    qattn_kernel<<<dim3(HW / 256, BATCH * HEADS), 256>>>();

    // out projection (tensor cores)
    gemm_out_kernel<<<dim3(HW / 128, CDIM / 128, BATCH), 256, GEMM_SMEM>>>();

    // final LN (single pass)
    ln_out_kernel<<<(BATCH * HW) / 32, 256, LN_SMEM>>>(out_norm_g, out);
}

// round 9
// speedup vs baseline: 2.0791x; 1.1228x over previous
#include <cuda_runtime.h>
#include <cuda_bf16.h>
#include <cuda_fp16.h>
#include <math.h>
#include <stdint.h>

#define BATCH 8
#define CDIM  512
#define INNER 256
#define QKV   768
#define HEADS 8
#define DH    32
#define HH    96
#define WW    96
#define HW    9216   // 96*96

// ---------------- scratch (static device globals) ---------------------------
__device__ __half g_xf [(size_t)BATCH * CDIM  * HW];   // LN(x) fp16
__device__ float g_qkv1[(size_t)BATCH * QKV   * HW];   // after 1x1
__device__ float g_qkv2[(size_t)BATCH * QKV   * HW];   // after dwconv3
__device__ __half g_af [(size_t)BATCH * INNER * HW];   // attn+silu fp16
__device__ float g_z   [(size_t)BATCH * CDIM  * HW];   // after out conv1x1
__device__ __half g_wh [(size_t)QKV * CDIM];           // qkv weights hi
__device__ __half g_wl [(size_t)QKV * CDIM];           // qkv weights lo
__device__ __half g_owh[(size_t)CDIM * INNER];         // out weights hi
__device__ __half g_owl[(size_t)CDIM * INNER];         // out weights lo
__device__ float g_krsum[BATCH * INNER];
__device__ float g_ctx  [BATCH * HEADS * DH * DH];
__device__ float g_ctxp [(size_t)9 * BATCH * HEADS * DH * DH];

__device__ __forceinline__ void split_f16(float v, __half& h, __half& l) {
    h = __float2half(v);
    l = __float2half(v - __half2float(h));
}

// ---------------- merged weight conversion (all four splits, same range) ----
__global__ void convert_w_kernel(const float* __restrict__ qw,
                                 const float* __restrict__ kw,
                                 const float* __restrict__ vw,
                                 const float* __restrict__ ow) {
    int i = blockIdx.x * blockDim.x + threadIdx.x;  // 0 .. INNER*CDIM-1
    split_f16(qw[i], g_wh[i], g_wl[i]);
    split_f16(kw[i], g_wh[i + INNER*CDIM], g_wl[i + INNER*CDIM]);
    split_f16(vw[i], g_wh[i + 2*INNER*CDIM], g_wl[i + 2*INNER*CDIM]);
    split_f16(ow[i], g_owh[i], g_owl[i]);              // CDIM*INNER == INNER*CDIM
}

// ---------------- single-pass channel LNs (smem-buffered) -------------------
__global__ void ln_in_kernel(const float* __restrict__ x,
                             const float* __restrict__ g) {
    extern __shared__ float s[];            // [512][33]
    __shared__ float s_mean[32], s_r[32];
    int t = threadIdx.x;
    int pos0 = blockIdx.x * 32;
    int b = pos0 / HW;
    int hw0 = pos0 - b * HW;
    int lane = t & 31, crow = t >> 5;
    #pragma unroll 8
    for (int it = 0; it < 64; it++) {
        int c = crow + it * 8;
        s[c * 33 + lane] = x[((size_t)b * CDIM + c) * HW + hw0 + lane];
    }
    __syncthreads();
    int p = t >> 3, sub = t & 7;            // 8 threads per position
    float sm = 0.f, sq = 0.f;
    #pragma unroll 8
    for (int j = 0; j < 64; j++) {
        float v = s[(sub + j * 8) * 33 + p];
        sm += v; sq += v * v;
    }
    #pragma unroll
    for (int off = 4; off > 0; off >>= 1) {
        sm += __shfl_xor_sync(0xffffffffu, sm, off);
        sq += __shfl_xor_sync(0xffffffffu, sq, off);
    }
    float mean = sm * (1.f / CDIM);
    float var  = sq * (1.f / CDIM) - mean * mean;
    float r = rsqrtf(var + 1e-5f);
    if (sub == 0) { s_mean[p] = mean; s_r[p] = r; }
    __syncthreads();
    float m2 = s_mean[lane], r2 = s_r[lane];
    #pragma unroll 8
    for (int it = 0; it < 64; it++) {
        int c = crow + it * 8;
        float y = (s[c * 33 + lane] - m2) * r2 * g[c];
        g_xf[((size_t)b * CDIM + c) * HW + hw0 + lane] = __float2half(y);
    }
}

__global__ void ln_out_kernel(const float* __restrict__ g,
                              float* __restrict__ out) {
    extern __shared__ float s[];            // [512][33]
    __shared__ float s_mean[32], s_r[32];
    int t = threadIdx.x;
    int pos0 = blockIdx.x * 32;
    int b = pos0 / HW;
    int hw0 = pos0 - b * HW;
    int lane = t & 31, crow = t >> 5;
    #pragma unroll 8
    for (int it = 0; it < 64; it++) {
        int c = crow + it * 8;
        s[c * 33 + lane] = g_z[((size_t)b * CDIM + c) * HW + hw0 + lane];
    }
    __syncthreads();
    int p = t >> 3, sub = t & 7;
    float sm = 0.f, sq = 0.f;
    #pragma unroll 8
    for (int j = 0; j < 64; j++) {
        float v = s[(sub + j * 8) * 33 + p];
        sm += v; sq += v * v;
    }
    #pragma unroll
    for (int off = 4; off > 0; off >>= 1) {
        sm += __shfl_xor_sync(0xffffffffu, sm, off);
        sq += __shfl_xor_sync(0xffffffffu, sq, off);
    }
    float mean = sm * (1.f / CDIM);
    float var  = sq * (1.f / CDIM) - mean * mean;
    float r = rsqrtf(var + 1e-5f);
    if (sub == 0) { s_mean[p] = mean; s_r[p] = r; }
    __syncthreads();
    float m2 = s_mean[lane], r2 = s_r[lane];
    #pragma unroll 8
    for (int it = 0; it < 64; it++) {
        int c = crow + it * 8;
        out[((size_t)b * CDIM + c) * HW + hw0 + lane] =
            (s[c * 33 + lane] - m2) * r2 * g[c];
    }
}

// ---------------- tensor-core GEMM (fp16 2-term weight split, BK=64) --------
// Y[b] = (Wh+Wl)[M,K] @ X[b][K,N], N = HW. Tile 128x128x64, 8 warps of 64x32.
__device__ __forceinline__ uint32_t sptr(const void* p) {
    return (uint32_t)__cvta_generic_to_shared(p);
}
__device__ __forceinline__ void cp_async16(void* sm, const void* gm) {
    asm volatile("cp.async.cg.shared.global [%0], [%1], 16;\n"
                 :: "r"(sptr(sm)), "l"(gm));
}
__device__ __forceinline__ void ldsm_x4(uint32_t* r, uint32_t a) {
    asm volatile("ldmatrix.sync.aligned.m8n8.x4.shared.b16 {%0,%1,%2,%3}, [%4];"
                 : "=r"(r[0]), "=r"(r[1]), "=r"(r[2]), "=r"(r[3]) : "r"(a));
}
__device__ __forceinline__ void ldsm_x2t(uint32_t* r, uint32_t a) {
    asm volatile("ldmatrix.sync.aligned.m8n8.x2.trans.shared.b16 {%0,%1}, [%2];"
                 : "=r"(r[0]), "=r"(r[1]) : "r"(a));
}
__device__ __forceinline__ void mma_f16(float* c, const uint32_t* a, const uint32_t* b) {
    asm volatile("mma.sync.aligned.m16n8k16.row.col.f32.f16.f16.f32 "
                 "{%0,%1,%2,%3},{%4,%5,%6,%7},{%8,%9},{%0,%1,%2,%3};"
                 : "+f"(c[0]), "+f"(c[1]), "+f"(c[2]), "+f"(c[3])
                 : "r"(a[0]), "r"(a[1]), "r"(a[2]), "r"(a[3]), "r"(b[0]), "r"(b[1]));
}

template<int M, int K>
__device__ __forceinline__ void mma_gemm_body(const __half* __restrict__ Wh,
                                              const __half* __restrict__ Wl,
                                              const __half* __restrict__ Xf,
                                              float* __restrict__ Y) {
    constexpr int N = HW;
    constexpr int BM = 128, BN = 128, BK = 64;
    constexpr int AP = BK + 8;      // 72 halves/row (144B): conflict-free ldsm
    constexpr int BP = BN + 8;      // 136 halves/row (272B)
    constexpr int A_SZ = BM * AP;   // 9216 halves/plane
    constexpr int B_SZ = BK * BP;   // 8704 halves
    constexpr int STAGE = 2 * A_SZ + B_SZ;   // 27136 halves = 54272 B
    constexpr int KC = K / BK;
    extern __shared__ __half smem[];

    int b = blockIdx.z;
    const __half* XfB = Xf + (size_t)b * K * N;
    float* Yb = Y + (size_t)b * M * N;
    int tm0 = blockIdx.y * BM;
    int tn0 = blockIdx.x * BN;
    int t = threadIdx.x;
    int lane = t & 31, warp = t >> 5;
    int wm = (warp & 1) * 64, wn = (warp >> 1) * 32;

    auto load_stage = [&](int kc, int s) {
        __half* sa_h = smem + (size_t)s * STAGE;
        __half* sa_l = sa_h + A_SZ;
        __half* sb   = sa_l + A_SZ;
        int k0 = kc * BK;
        #pragma unroll
        for (int i = 0; i < 4; i++) {
            int c = t + i * 256;            // 0..1023
            int m  = c >> 3, kk = (c & 7) * 8;
            cp_async16(&sa_h[m * AP + kk], &Wh[(size_t)(tm0 + m) * K + k0 + kk]);
            cp_async16(&sa_l[m * AP + kk], &Wl[(size_t)(tm0 + m) * K + k0 + kk]);
            int kr = c >> 4, nn = (c & 15) * 8;
            cp_async16(&sb[kr * BP + nn], &XfB[(size_t)(k0 + kr) * N + tn0 + nn]);
        }
        asm volatile("cp.async.commit_group;");
    };

    float acc[4][4][4];
    #pragma unroll
    for (int i = 0; i < 4; i++)
        #pragma unroll
        for (int j = 0; j < 4; j++)
            #pragma unroll
            for (int r = 0; r < 4; r++) acc[i][j][r] = 0.f;

    load_stage(0, 0);
    for (int kc = 0; kc < KC; kc++) {
        int s = kc & 1;
        asm volatile("cp.async.wait_group 0;");
        __syncthreads();
        if (kc + 1 < KC) load_stage(kc + 1, s ^ 1);

        __half* sa_h = smem + (size_t)s * STAGE;
        __half* sa_l = sa_h + A_SZ;
        __half* sb   = sa_l + A_SZ;

        #pragma unroll
        for (int ks = 0; ks < 4; ks++) {
            uint32_t bx[4][2];
            int brow = ks * 16 + (lane & 15);
            #pragma unroll
            for (int nt = 0; nt < 4; nt++)
                ldsm_x2t(bx[nt], sptr(&sb[brow * BP + wn + nt * 8]));
            uint32_t a[4][4];
            int arow = lane & 15;
            int acol = ks * 16 + (lane >> 4) * 8;
            #pragma unroll
            for (int mt = 0; mt < 4; mt++)
                ldsm_x4(a[mt], sptr(&sa_h[(wm + mt * 16 + arow) * AP + acol]));
            #pragma unroll
            for (int mt = 0; mt < 4; mt++)
                #pragma unroll
                for (int nt = 0; nt < 4; nt++)
                    mma_f16(acc[mt][nt], a[mt], bx[nt]);
            #pragma unroll
            for (int mt = 0; mt < 4; mt++)
                ldsm_x4(a[mt], sptr(&sa_l[(wm + mt * 16 + arow) * AP + acol]));
            #pragma unroll
            for (int mt = 0; mt < 4; mt++)
                #pragma unroll
                for (int nt = 0; nt < 4; nt++)
                    mma_f16(acc[mt][nt], a[mt], bx[nt]);
        }
    }

    #pragma unroll
    for (int mt = 0; mt < 4; mt++)
        #pragma unroll
        for (int nt = 0; nt < 4; nt++) {
            int m = tm0 + wm + mt * 16 + (lane >> 2);
            int n = tn0 + wn + nt * 8 + (lane & 3) * 2;
            *(float2*)&Yb[(size_t)m * N + n]       = make_float2(acc[mt][nt][0], acc[mt][nt][1]);
            *(float2*)&Yb[(size_t)(m + 8) * N + n] = make_float2(acc[mt][nt][2], acc[mt][nt][3]);
        }
}

// wrappers: device-global pointers resolved in device code
__global__ void __launch_bounds__(256) gemm_qkv_kernel() {
    mma_gemm_body<QKV, CDIM>(g_wh, g_wl, g_xf, g_qkv1);
}
__global__ void __launch_bounds__(256) gemm_out_kernel() {
    mma_gemm_body<CDIM, INNER>(g_owh, g_owl, g_af, g_z);
}

// ---------------- depthwise 3x3, half-image tiles, float4 loads -------------
// Block: (96,4) = 384 threads. Each block: one channel, 48 output rows
// (+1 halo row each side). Smem data region starts at column 4 (16B aligned);
// zero halo columns at 3 and 100.
__global__ void dwconv3_kernel(const float* __restrict__ qwd,
                               const float* __restrict__ kwd,
                               const float* __restrict__ vwd) {
    __shared__ float s[50][104];
    int bc = blockIdx.x;              // b*QKV + c
    int half = blockIdx.y;            // 0: rows 0-47, 1: rows 48-95
    int h0 = half * 48;
    int c = bc % QKV;
    const float* wp = (c < 256) ? (qwd + c * 9)
                    : (c < 512) ? (kwd + (c - 256) * 9)
                                : (vwd + (c - 512) * 9);
    float w0 = wp[0], w1 = wp[1], w2 = wp[2];
    float w3 = wp[3], w4 = wp[4], w5 = wp[5];
    float w6 = wp[6], w7 = wp[7], w8 = wp[8];
    const float* ip = g_qkv1 + (size_t)bc * HW;
    int tx = threadIdx.x;  // 0..95
    int ty = threadIdx.y;  // 0..3
    int tid = ty * 96 + tx;

    // halo columns
    for (int r = tid; r < 50; r += 384) { s[r][3] = 0.f; s[r][100] = 0.f; }
    // vectorized image load: 50 rows x 24 float4
    for (int i = tid; i < 50 * 24; i += 384) {
        int r = i / 24, c4 = i % 24;
        int hg = h0 - 1 + r;
        float4 v = (hg >= 0 && hg < HH)
                 ? *(const float4*)(ip + (size_t)hg * WW + c4 * 4)
                 : make_float4(0.f, 0.f, 0.f, 0.f);
        *(float4*)&s[r][4 + c4 * 4] = v;
    }
    __syncthreads();

    float* op = g_qkv2 + (size_t)bc * HW + (size_t)h0 * WW;
    #pragma unroll
    for (int g = 0; g < 12; g++) {
        int hl = g * 4 + ty;          // local output row 0..47
        int r = hl + 1;               // smem row
        int wcol = 4 + tx;
        float acc = w0 * s[r - 1][wcol - 1] + w1 * s[r - 1][wcol] + w2 * s[r - 1][wcol + 1]
                  + w3 * s[r    ][wcol - 1] + w4 * s[r    ][wcol] + w5 * s[r    ][wcol + 1]
                  + w6 * s[r + 1][wcol - 1] + w7 * s[r + 1][wcol] + w8 * s[r + 1][wcol + 1];
        op[hl * WW + tx] = acc;
    }
}

// ---------------- k softmax: single pass sum(exp) (values tiny; no max) -----
__global__ void kstats_kernel() {
    int bc = blockIdx.x;            // 0 .. BATCH*INNER-1
    int b = bc / INNER, c = bc % INNER;
    const float* kp = g_qkv2 + ((size_t)b * QKV + INNER + c) * HW;
    int t = threadIdx.x;
    __shared__ float sm[256];
    float sum = 0.f;
    for (int i = t; i < HW; i += 256) sum += __expf(kp[i]);
    sm[t] = sum; __syncthreads();
    for (int s = 128; s > 0; s >>= 1) { if (t < s) sm[t] += sm[t + s]; __syncthreads(); }
    if (t == 0) g_krsum[bc] = 1.0f / sm[0];
}

// ---------------- context = softmax_k^T @ v, partial over n-chunks ----------
__global__ void context_part_kernel() {
    int bh = blockIdx.x;
    int chunk = blockIdx.y;          // 0..8, 1024 positions each
    int b = bh / HEADS, h = bh % HEADS;
    const float* kp = g_qkv2 + ((size_t)b * QKV + INNER + h * DH) * HW;
    const float* vp = g_qkv2 + ((size_t)b * QKV + 2 * INNER + h * DH) * HW;
    const float* kr = g_krsum + b * INNER + h * DH;
    __shared__ float sk[DH][33];
    __shared__ float sv[DH][33];
    int t = threadIdx.x;             // 256
    int e = t & 31;
    int d0 = (t >> 5) * 4;
    float acc0 = 0.f, acc1 = 0.f, acc2 = 0.f, acc3 = 0.f;
    int nbeg = chunk * 1024, nend = nbeg + 1024;
    for (int n0 = nbeg; n0 < nend; n0 += 32) {
        #pragma unroll
        for (int i = 0; i < 4; i++) {
            int idx = t + i * 256;
            int d = idx >> 5, nn = idx & 31;
            float kv = kp[(size_t)d * HW + n0 + nn];
            sk[d][nn] = __expf(kv) * kr[d];
            sv[d][nn] = vp[(size_t)d * HW + n0 + nn];
        }
        __syncthreads();
        #pragma unroll
        for (int nn = 0; nn < 32; nn++) {
            float vv = sv[e][nn];
            acc0 += sk[d0 + 0][nn] * vv;
            acc1 += sk[d0 + 1][nn] * vv;
            acc2 += sk[d0 + 2][nn] * vv;
            acc3 += sk[d0 + 3][nn] * vv;
        }
        __syncthreads();
    }
    float* cp = g_ctxp + ((size_t)chunk * BATCH * HEADS + bh) * DH * DH;
    cp[(d0 + 0) * DH + e] = acc0;
    cp[(d0 + 1) * DH + e] = acc1;
    cp[(d0 + 2) * DH + e] = acc2;
    cp[(d0 + 3) * DH + e] = acc3;
}
__global__ void context_reduce_kernel() {
    int bh = blockIdx.x;
    int i = threadIdx.x;             // 1024
    float s = 0.f;
    #pragma unroll
    for (int c = 0; c < 9; c++)
        s += g_ctxp[((size_t)c * BATCH * HEADS + bh) * DH * DH + i];
    g_ctx[(size_t)bh * DH * DH + i] = s;
}

// ---------------- q softmax @ context + silu -> fp16 ------------------------
__global__ void qattn_kernel() {
    int bh = blockIdx.y;
    int b = bh / HEADS, h = bh % HEADS;
    int n = blockIdx.x * 256 + threadIdx.x;
    __shared__ float sctx[DH][DH];
    for (int i = threadIdx.x; i < DH * DH; i += 256)
        sctx[i / DH][i % DH] = g_ctx[(size_t)bh * DH * DH + i];
    __syncthreads();
    const float* qp = g_qkv2 + ((size_t)b * QKV + h * DH) * HW + n;
    float qv[DH];
    float m = -1e30f;
    #pragma unroll
    for (int d = 0; d < DH; d++) { qv[d] = qp[(size_t)d * HW]; m = fmaxf(m, qv[d]); }
    float sum = 0.f;
    #pragma unroll
    for (int d = 0; d < DH; d++) { qv[d] = __expf(qv[d] - m); sum += qv[d]; }
    float sc = 0.17677669529663688f / sum;  // (1/sqrt(32)) / sum
    #pragma unroll
    for (int d = 0; d < DH; d++) qv[d] *= sc;
    size_t obase = ((size_t)b * INNER + h * DH) * HW + n;
    #pragma unroll
    for (int e = 0; e < DH; e++) {
        float o = 0.f;
        #pragma unroll
        for (int d = 0; d < DH; d++) o += qv[d] * sctx[d][e];
        o = o / (1.0f + __expf(-o));   // silu
        g_af[obase + (size_t)e * HW] = __float2half(o);
    }
}

// ---------------- launch ----------------------------------------------------
extern "C" void kernel_launch(void* const* d_in, const int* in_sizes, int n_in,
                              void* d_out, int out_size) {
    const float* fmap       = (const float*)d_in[0];
    const float* norm_g     = (const float*)d_in[1];
    const float* q_w1       = (const float*)d_in[2];
    const float* q_wd       = (const float*)d_in[3];
    const float* k_w1       = (const float*)d_in[4];
    const float* k_wd       = (const float*)d_in[5];
    const float* v_w1       = (const float*)d_in[6];
    const float* v_wd       = (const float*)d_in[7];
    const float* out_w      = (const float*)d_in[8];
    const float* out_norm_g = (const float*)d_in[9];
    float* out = (float*)d_out;

    // GEMM smem: 2 stages * (2*128*72 + 64*136) halves * 2B = 108544
    const int GEMM_SMEM = 2 * (2 * 128 * 72 + 64 * 136) * 2;
    const int LN_SMEM = 512 * 33 * 4;   // 67584
    cudaFuncSetAttribute(gemm_qkv_kernel,
                         cudaFuncAttributeMaxDynamicSharedMemorySize, GEMM_SMEM);
    cudaFuncSetAttribute(gemm_out_kernel,
                         cudaFuncAttributeMaxDynamicSharedMemorySize, GEMM_SMEM);
    cudaFuncSetAttribute(ln_in_kernel,
                         cudaFuncAttributeMaxDynamicSharedMemorySize, LN_SMEM);
    cudaFuncSetAttribute(ln_out_kernel,
                         cudaFuncAttributeMaxDynamicSharedMemorySize, LN_SMEM);

    // fp16-pair weights (all four tensors, one kernel)
    convert_w_kernel<<<(INNER * CDIM) / 256, 256>>>(q_w1, k_w1, v_w1, out_w);

    // input LN -> fp16 plane (single pass)
    ln_in_kernel<<<(BATCH * HW) / 32, 256, LN_SMEM>>>(fmap, norm_g);

    // qkv = Wqkv @ xn  (tensor cores)
    gemm_qkv_kernel<<<dim3(HW / 128, QKV / 128, BATCH), 256, GEMM_SMEM>>>();

    // depthwise 3x3 (half image per block, float4 loads)
    dwconv3_kernel<<<dim3(BATCH * QKV, 2), dim3(96, 4)>>>(q_wd, k_wd, v_wd);

    // attention
    kstats_kernel<<<BATCH * INNER, 256>>>();
    context_part_kernel<<<dim3(BATCH * HEADS, 9), 256>>>();
    context_reduce_kernel<<<BATCH * HEADS, 1024>>>();
    qattn_kernel<<<dim3(HW / 256, BATCH * HEADS), 256>>>();

    // out projection (tensor cores)
    gemm_out_kernel<<<dim3(HW / 128, CDIM / 128, BATCH), 256, GEMM_SMEM>>>();

    // final LN (single pass)
    ln_out_kernel<<<(BATCH * HW) / 32, 256, LN_SMEM>>>(out_norm_g, out);
}

// round 10
// speedup vs baseline: 2.1722x; 1.0447x over previous
#include <cuda_runtime.h>
#include <cuda_bf16.h>
#include <cuda_fp16.h>
#include <math.h>
#include <stdint.h>

#define BATCH 8
#define CDIM  512
#define INNER 256
#define QKV   768
#define HEADS 8
#define DH    32
#define HH    96
#define WW    96
#define HW    9216   // 96*96

// ---------------- scratch (static device globals) ---------------------------
__device__ __half g_xf [(size_t)BATCH * CDIM  * HW];   // LN(x) fp16
__device__ float g_qkv1[(size_t)BATCH * QKV   * HW];   // after 1x1
__device__ float g_qkv2[(size_t)BATCH * QKV   * HW];   // after dwconv3
__device__ __half g_af [(size_t)BATCH * INNER * HW];   // attn+silu fp16
__device__ float g_z   [(size_t)BATCH * CDIM  * HW];   // after out conv1x1
__device__ __half g_wh [(size_t)QKV * CDIM];           // qkv weights hi
__device__ __half g_wl [(size_t)QKV * CDIM];           // qkv weights lo
__device__ __half g_owh[(size_t)CDIM * INNER];         // out weights hi
__device__ __half g_owl[(size_t)CDIM * INNER];         // out weights lo
__device__ float g_ksum [BATCH * INNER];
__device__ float g_krsum[BATCH * INNER];
__device__ float g_ctxp [(size_t)9 * BATCH * HEADS * DH * DH];

__device__ __forceinline__ void split_f16(float v, __half& h, __half& l) {
    h = __float2half(v);
    l = __float2half(v - __half2float(h));
}

// ---------------- merged weight conversion + ksum zeroing -------------------
__global__ void convert_w_kernel(const float* __restrict__ qw,
                                 const float* __restrict__ kw,
                                 const float* __restrict__ vw,
                                 const float* __restrict__ ow) {
    int i = blockIdx.x * blockDim.x + threadIdx.x;  // 0 .. INNER*CDIM-1
    split_f16(qw[i], g_wh[i], g_wl[i]);
    split_f16(kw[i], g_wh[i + INNER*CDIM], g_wl[i + INNER*CDIM]);
    split_f16(vw[i], g_wh[i + 2*INNER*CDIM], g_wl[i + 2*INNER*CDIM]);
    split_f16(ow[i], g_owh[i], g_owl[i]);              // CDIM*INNER == INNER*CDIM
    if (i < BATCH * INNER) g_ksum[i] = 0.f;            // zero each replay
}

// ---------------- single-pass channel LNs (smem-buffered) -------------------
__global__ void ln_in_kernel(const float* __restrict__ x,
                             const float* __restrict__ g) {
    extern __shared__ float s[];            // [512][33]
    __shared__ float s_mean[32], s_r[32];
    int t = threadIdx.x;
    int pos0 = blockIdx.x * 32;
    int b = pos0 / HW;
    int hw0 = pos0 - b * HW;
    int lane = t & 31, crow = t >> 5;
    #pragma unroll 8
    for (int it = 0; it < 64; it++) {
        int c = crow + it * 8;
        s[c * 33 + lane] = x[((size_t)b * CDIM + c) * HW + hw0 + lane];
    }
    __syncthreads();
    int p = t >> 3, sub = t & 7;            // 8 threads per position
    float sm = 0.f, sq = 0.f;
    #pragma unroll 8
    for (int j = 0; j < 64; j++) {
        float v = s[(sub + j * 8) * 33 + p];
        sm += v; sq += v * v;
    }
    #pragma unroll
    for (int off = 4; off > 0; off >>= 1) {
        sm += __shfl_xor_sync(0xffffffffu, sm, off);
        sq += __shfl_xor_sync(0xffffffffu, sq, off);
    }
    float mean = sm * (1.f / CDIM);
    float var  = sq * (1.f / CDIM) - mean * mean;
    float r = rsqrtf(var + 1e-5f);
    if (sub == 0) { s_mean[p] = mean; s_r[p] = r; }
    __syncthreads();
    float m2 = s_mean[lane], r2 = s_r[lane];
    #pragma unroll 8
    for (int it = 0; it < 64; it++) {
        int c = crow + it * 8;
        float y = (s[c * 33 + lane] - m2) * r2 * g[c];
        g_xf[((size_t)b * CDIM + c) * HW + hw0 + lane] = __float2half(y);
    }
}

__global__ void ln_out_kernel(const float* __restrict__ g,
                              float* __restrict__ out) {
    extern __shared__ float s[];            // [512][33]
    __shared__ float s_mean[32], s_r[32];
    int t = threadIdx.x;
    int pos0 = blockIdx.x * 32;
    int b = pos0 / HW;
    int hw0 = pos0 - b * HW;
    int lane = t & 31, crow = t >> 5;
    #pragma unroll 8
    for (int it = 0; it < 64; it++) {
        int c = crow + it * 8;
        s[c * 33 + lane] = g_z[((size_t)b * CDIM + c) * HW + hw0 + lane];
    }
    __syncthreads();
    int p = t >> 3, sub = t & 7;
    float sm = 0.f, sq = 0.f;
    #pragma unroll 8
    for (int j = 0; j < 64; j++) {
        float v = s[(sub + j * 8) * 33 + p];
        sm += v; sq += v * v;
    }
    #pragma unroll
    for (int off = 4; off > 0; off >>= 1) {
        sm += __shfl_xor_sync(0xffffffffu, sm, off);
        sq += __shfl_xor_sync(0xffffffffu, sq, off);
    }
    float mean = sm * (1.f / CDIM);
    float var  = sq * (1.f / CDIM) - mean * mean;
    float r = rsqrtf(var + 1e-5f);
    if (sub == 0) { s_mean[p] = mean; s_r[p] = r; }
    __syncthreads();
    float m2 = s_mean[lane], r2 = s_r[lane];
    #pragma unroll 8
    for (int it = 0; it < 64; it++) {
        int c = crow + it * 8;
        out[((size_t)b * CDIM + c) * HW + hw0 + lane] =
            (s[c * 33 + lane] - m2) * r2 * g[c];
    }
}

// ---------------- tensor-core GEMM (fp16 2-term weight split, BK=64) --------
__device__ __forceinline__ uint32_t sptr(const void* p) {
    return (uint32_t)__cvta_generic_to_shared(p);
}
__device__ __forceinline__ void cp_async16(void* sm, const void* gm) {
    asm volatile("cp.async.cg.shared.global [%0], [%1], 16;\n"
                 :: "r"(sptr(sm)), "l"(gm));
}
__device__ __forceinline__ void ldsm_x4(uint32_t* r, uint32_t a) {
    asm volatile("ldmatrix.sync.aligned.m8n8.x4.shared.b16 {%0,%1,%2,%3}, [%4];"
                 : "=r"(r[0]), "=r"(r[1]), "=r"(r[2]), "=r"(r[3]) : "r"(a));
}
__device__ __forceinline__ void ldsm_x2t(uint32_t* r, uint32_t a) {
    asm volatile("ldmatrix.sync.aligned.m8n8.x2.trans.shared.b16 {%0,%1}, [%2];"
                 : "=r"(r[0]), "=r"(r[1]) : "r"(a));
}
__device__ __forceinline__ void mma_f16(float* c, const uint32_t* a, const uint32_t* b) {
    asm volatile("mma.sync.aligned.m16n8k16.row.col.f32.f16.f16.f32 "
                 "{%0,%1,%2,%3},{%4,%5,%6,%7},{%8,%9},{%0,%1,%2,%3};"
                 : "+f"(c[0]), "+f"(c[1]), "+f"(c[2]), "+f"(c[3])
                 : "r"(a[0]), "r"(a[1]), "r"(a[2]), "r"(a[3]), "r"(b[0]), "r"(b[1]));
}

template<int M, int K>
__device__ __forceinline__ void mma_gemm_body(const __half* __restrict__ Wh,
                                              const __half* __restrict__ Wl,
                                              const __half* __restrict__ Xf,
                                              float* __restrict__ Y) {
    constexpr int N = HW;
    constexpr int BM = 128, BN = 128, BK = 64;
    constexpr int AP = BK + 8;      // 72 halves/row (144B): conflict-free ldsm
    constexpr int BP = BN + 8;      // 136 halves/row (272B)
    constexpr int A_SZ = BM * AP;   // 9216 halves/plane
    constexpr int B_SZ = BK * BP;   // 8704 halves
    constexpr int STAGE = 2 * A_SZ + B_SZ;   // 27136 halves = 54272 B
    constexpr int KC = K / BK;
    extern __shared__ __half smem[];

    int b = blockIdx.z;
    const __half* XfB = Xf + (size_t)b * K * N;
    float* Yb = Y + (size_t)b * M * N;
    int tm0 = blockIdx.y * BM;
    int tn0 = blockIdx.x * BN;
    int t = threadIdx.x;
    int lane = t & 31, warp = t >> 5;
    int wm = (warp & 1) * 64, wn = (warp >> 1) * 32;

    auto load_stage = [&](int kc, int s) {
        __half* sa_h = smem + (size_t)s * STAGE;
        __half* sa_l = sa_h + A_SZ;
        __half* sb   = sa_l + A_SZ;
        int k0 = kc * BK;
        #pragma unroll
        for (int i = 0; i < 4; i++) {
            int c = t + i * 256;            // 0..1023
            int m  = c >> 3, kk = (c & 7) * 8;
            cp_async16(&sa_h[m * AP + kk], &Wh[(size_t)(tm0 + m) * K + k0 + kk]);
            cp_async16(&sa_l[m * AP + kk], &Wl[(size_t)(tm0 + m) * K + k0 + kk]);
            int kr = c >> 4, nn = (c & 15) * 8;
            cp_async16(&sb[kr * BP + nn], &XfB[(size_t)(k0 + kr) * N + tn0 + nn]);
        }
        asm volatile("cp.async.commit_group;");
    };

    float acc[4][4][4];
    #pragma unroll
    for (int i = 0; i < 4; i++)
        #pragma unroll
        for (int j = 0; j < 4; j++)
            #pragma unroll
            for (int r = 0; r < 4; r++) acc[i][j][r] = 0.f;

    load_stage(0, 0);
    for (int kc = 0; kc < KC; kc++) {
        int s = kc & 1;
        asm volatile("cp.async.wait_group 0;");
        __syncthreads();
        if (kc + 1 < KC) load_stage(kc + 1, s ^ 1);

        __half* sa_h = smem + (size_t)s * STAGE;
        __half* sa_l = sa_h + A_SZ;
        __half* sb   = sa_l + A_SZ;

        #pragma unroll
        for (int ks = 0; ks < 4; ks++) {
            uint32_t bx[4][2];
            int brow = ks * 16 + (lane & 15);
            #pragma unroll
            for (int nt = 0; nt < 4; nt++)
                ldsm_x2t(bx[nt], sptr(&sb[brow * BP + wn + nt * 8]));
            uint32_t a[4][4];
            int arow = lane & 15;
            int acol = ks * 16 + (lane >> 4) * 8;
            #pragma unroll
            for (int mt = 0; mt < 4; mt++)
                ldsm_x4(a[mt], sptr(&sa_h[(wm + mt * 16 + arow) * AP + acol]));
            #pragma unroll
            for (int mt = 0; mt < 4; mt++)
                #pragma unroll
                for (int nt = 0; nt < 4; nt++)
                    mma_f16(acc[mt][nt], a[mt], bx[nt]);
            #pragma unroll
            for (int mt = 0; mt < 4; mt++)
                ldsm_x4(a[mt], sptr(&sa_l[(wm + mt * 16 + arow) * AP + acol]));
            #pragma unroll
            for (int mt = 0; mt < 4; mt++)
                #pragma unroll
                for (int nt = 0; nt < 4; nt++)
                    mma_f16(acc[mt][nt], a[mt], bx[nt]);
        }
    }

    #pragma unroll
    for (int mt = 0; mt < 4; mt++)
        #pragma unroll
        for (int nt = 0; nt < 4; nt++) {
            int m = tm0 + wm + mt * 16 + (lane >> 2);
            int n = tn0 + wn + nt * 8 + (lane & 3) * 2;
            *(float2*)&Yb[(size_t)m * N + n]       = make_float2(acc[mt][nt][0], acc[mt][nt][1]);
            *(float2*)&Yb[(size_t)(m + 8) * N + n] = make_float2(acc[mt][nt][2], acc[mt][nt][3]);
        }
}

__global__ void __launch_bounds__(256) gemm_qkv_kernel() {
    mma_gemm_body<QKV, CDIM>(g_wh, g_wl, g_xf, g_qkv1);
}
__global__ void __launch_bounds__(256) gemm_out_kernel() {
    mma_gemm_body<CDIM, INNER>(g_owh, g_owl, g_af, g_z);
}

// ---------------- depthwise 3x3: rolling window + fused k-softmax sum -------
// Block (96,4): thread = one column, 12 consecutive rows, 3x3 register window
// (3 LDS per new row instead of 9). k-channel blocks accumulate sum(exp(out))
// and atomicAdd once per block (2 blocks/channel: commutative -> deterministic).
__global__ void dwconv3_kernel(const float* __restrict__ qwd,
                               const float* __restrict__ kwd,
                               const float* __restrict__ vwd) {
    __shared__ float s[50][104];
    __shared__ float red[384];
    int bc = blockIdx.x;              // b*QKV + c
    int half = blockIdx.y;            // 0: rows 0-47, 1: rows 48-95
    int h0 = half * 48;
    int c = bc % QKV;
    const float* wp = (c < 256) ? (qwd + c * 9)
                    : (c < 512) ? (kwd + (c - 256) * 9)
                                : (vwd + (c - 512) * 9);
    float w0 = wp[0], w1 = wp[1], w2 = wp[2];
    float w3 = wp[3], w4 = wp[4], w5 = wp[5];
    float w6 = wp[6], w7 = wp[7], w8 = wp[8];
    const float* ip = g_qkv1 + (size_t)bc * HW;
    int tx = threadIdx.x;  // 0..95
    int ty = threadIdx.y;  // 0..3
    int tid = ty * 96 + tx;

    for (int r = tid; r < 50; r += 384) { s[r][3] = 0.f; s[r][100] = 0.f; }
    for (int i = tid; i < 50 * 24; i += 384) {
        int r = i / 24, c4 = i % 24;
        int hg = h0 - 1 + r;
        float4 v = (hg >= 0 && hg < HH)
                 ? *(const float4*)(ip + (size_t)hg * WW + c4 * 4)
                 : make_float4(0.f, 0.f, 0.f, 0.f);
        *(float4*)&s[r][4 + c4 * 4] = v;
    }
    __syncthreads();

    float* op = g_qkv2 + (size_t)bc * HW + (size_t)h0 * WW;
    int wcol = 4 + tx;
    int base = ty * 12;               // local rows base..base+11
    bool is_k = (c >= INNER && c < 2 * INNER);
    float ksum = 0.f;

    float a0 = s[base][wcol - 1],     a1 = s[base][wcol],     a2 = s[base][wcol + 1];
    float b0 = s[base + 1][wcol - 1], b1 = s[base + 1][wcol], b2 = s[base + 1][wcol + 1];
    #pragma unroll
    for (int i = 0; i < 12; i++) {
        int hl = base + i;
        int r = hl + 2;
        float c0 = s[r][wcol - 1], c1 = s[r][wcol], c2 = s[r][wcol + 1];
        float acc = w0 * a0 + w1 * a1 + w2 * a2
                  + w3 * b0 + w4 * b1 + w5 * b2
                  + w6 * c0 + w7 * c1 + w8 * c2;
        op[hl * WW + tx] = acc;
        if (is_k) ksum += __expf(acc);
        a0 = b0; a1 = b1; a2 = b2;
        b0 = c0; b1 = c1; b2 = c2;
    }

    if (is_k) {
        red[tid] = ksum;
        __syncthreads();
        if (tid < 128) red[tid] += red[tid + 128] + red[tid + 256];
        __syncthreads();
        for (int st = 64; st > 0; st >>= 1) {
            if (tid < st) red[tid] += red[tid + st];
            __syncthreads();
        }
        if (tid == 0)
            atomicAdd(&g_ksum[(bc / QKV) * INNER + (c - INNER)], red[0]);
    }
}

// ---------------- reciprocal of k-softmax sums ------------------------------
__global__ void krecip_kernel() {
    int i = blockIdx.x * blockDim.x + threadIdx.x;   // 0..2047
    g_krsum[i] = 1.0f / g_ksum[i];
}

// ---------------- context = softmax_k^T @ v, partial over n-chunks ----------
__global__ void context_part_kernel() {
    int bh = blockIdx.x;
    int chunk = blockIdx.y;          // 0..8, 1024 positions each
    int b = bh / HEADS, h = bh % HEADS;
    const float* kp = g_qkv2 + ((size_t)b * QKV + INNER + h * DH) * HW;
    const float* vp = g_qkv2 + ((size_t)b * QKV + 2 * INNER + h * DH) * HW;
    const float* kr = g_krsum + b * INNER + h * DH;
    __shared__ float sk[DH][33];
    __shared__ float sv[DH][33];
    int t = threadIdx.x;             // 256
    int e = t & 31;
    int d0 = (t >> 5) * 4;
    float acc0 = 0.f, acc1 = 0.f, acc2 = 0.f, acc3 = 0.f;
    int nbeg = chunk * 1024, nend = nbeg + 1024;
    for (int n0 = nbeg; n0 < nend; n0 += 32) {
        #pragma unroll
        for (int i = 0; i < 4; i++) {
            int idx = t + i * 256;
            int d = idx >> 5, nn = idx & 31;
            float kv = kp[(size_t)d * HW + n0 + nn];
            sk[d][nn] = __expf(kv) * kr[d];
            sv[d][nn] = vp[(size_t)d * HW + n0 + nn];
        }
        __syncthreads();
        #pragma unroll
        for (int nn = 0; nn < 32; nn++) {
            float vv = sv[e][nn];
            acc0 += sk[d0 + 0][nn] * vv;
            acc1 += sk[d0 + 1][nn] * vv;
            acc2 += sk[d0 + 2][nn] * vv;
            acc3 += sk[d0 + 3][nn] * vv;
        }
        __syncthreads();
    }
    float* cp = g_ctxp + ((size_t)chunk * BATCH * HEADS + bh) * DH * DH;
    cp[(d0 + 0) * DH + e] = acc0;
    cp[(d0 + 1) * DH + e] = acc1;
    cp[(d0 + 2) * DH + e] = acc2;
    cp[(d0 + 3) * DH + e] = acc3;
}

// ---------------- q softmax @ context + silu -> fp16 (inline ctx reduce) ----
__global__ void qattn_kernel() {
    int bh = blockIdx.y;
    int b = bh / HEADS, h = bh % HEADS;
    int n = blockIdx.x * 256 + threadIdx.x;
    __shared__ float sctx[DH][DH];
    for (int i = threadIdx.x; i < DH * DH; i += 256) {
        float ssum = 0.f;
        #pragma unroll
        for (int cc = 0; cc < 9; cc++)
            ssum += g_ctxp[((size_t)cc * BATCH * HEADS + bh) * DH * DH + i];
        sctx[i / DH][i % DH] = ssum;
    }
    __syncthreads();
    const float* qp = g_qkv2 + ((size_t)b * QKV + h * DH) * HW + n;
    float qv[DH];
    float m = -1e30f;
    #pragma unroll
    for (int d = 0; d < DH; d++) { qv[d] = qp[(size_t)d * HW]; m = fmaxf(m, qv[d]); }
    float sum = 0.f;
    #pragma unroll
    for (int d = 0; d < DH; d++) { qv[d] = __expf(qv[d] - m); sum += qv[d]; }
    float sc = 0.17677669529663688f / sum;  // (1/sqrt(32)) / sum
    #pragma unroll
    for (int d = 0; d < DH; d++) qv[d] *= sc;
    size_t obase = ((size_t)b * INNER + h * DH) * HW + n;
    #pragma unroll
    for (int e = 0; e < DH; e++) {
        float o = 0.f;
        #pragma unroll
        for (int d = 0; d < DH; d++) o += qv[d] * sctx[d][e];
        o = o / (1.0f + __expf(-o));   // silu
        g_af[obase + (size_t)e * HW] = __float2half(o);
    }
}

// ---------------- launch ----------------------------------------------------
extern "C" void kernel_launch(void* const* d_in, const int* in_sizes, int n_in,
                              void* d_out, int out_size) {
    const float* fmap       = (const float*)d_in[0];
    const float* norm_g     = (const float*)d_in[1];
    const float* q_w1       = (const float*)d_in[2];
    const float* q_wd       = (const float*)d_in[3];
    const float* k_w1       = (const float*)d_in[4];
    const float* k_wd       = (const float*)d_in[5];
    const float* v_w1       = (const float*)d_in[6];
    const float* v_wd       = (const float*)d_in[7];
    const float* out_w      = (const float*)d_in[8];
    const float* out_norm_g = (const float*)d_in[9];
    float* out = (float*)d_out;

    // GEMM smem: 2 stages * (2*128*72 + 64*136) halves * 2B = 108544
    const int GEMM_SMEM = 2 * (2 * 128 * 72 + 64 * 136) * 2;
    const int LN_SMEM = 512 * 33 * 4;   // 67584
    cudaFuncSetAttribute(gemm_qkv_kernel,
                         cudaFuncAttributeMaxDynamicSharedMemorySize, GEMM_SMEM);
    cudaFuncSetAttribute(gemm_out_kernel,
                         cudaFuncAttributeMaxDynamicSharedMemorySize, GEMM_SMEM);
    cudaFuncSetAttribute(ln_in_kernel,
                         cudaFuncAttributeMaxDynamicSharedMemorySize, LN_SMEM);
    cudaFuncSetAttribute(ln_out_kernel,
                         cudaFuncAttributeMaxDynamicSharedMemorySize, LN_SMEM);

    // fp16-pair weights + g_ksum zeroing (runs first every replay)
    convert_w_kernel<<<(INNER * CDIM) / 256, 256>>>(q_w1, k_w1, v_w1, out_w);

    // input LN -> fp16 plane (single pass)
    ln_in_kernel<<<(BATCH * HW) / 32, 256, LN_SMEM>>>(fmap, norm_g);

    // qkv = Wqkv @ xn  (tensor cores)
    gemm_qkv_kernel<<<dim3(HW / 128, QKV / 128, BATCH), 256, GEMM_SMEM>>>();

    // depthwise 3x3 (rolling window) + fused k-softmax sum
    dwconv3_kernel<<<dim3(BATCH * QKV, 2), dim3(96, 4)>>>(q_wd, k_wd, v_wd);

    // attention
    krecip_kernel<<<(BATCH * INNER) / 256, 256>>>();
    context_part_kernel<<<dim3(BATCH * HEADS, 9), 256>>>();
    qattn_kernel<<<dim3(HW / 256, BATCH * HEADS), 256>>>();

    // out projection (tensor cores)
    gemm_out_kernel<<<dim3(HW / 128, CDIM / 128, BATCH), 256, GEMM_SMEM>>>();

    // final LN (single pass)
    ln_out_kernel<<<(BATCH * HW) / 32, 256, LN_SMEM>>>(out_norm_g, out);
}